// round 7
// baseline (speedup 1.0000x reference)
#include <cuda_runtime.h>
#include <math.h>

#define BB   32
#define TT   512
#define LAT  256
#define HID  1024
#define HO   512
#define G3   1536
#define MTOT (BB*TT)

// GRU partitioning: 4 independent groups x 8 batches, 32 CTAs per group.
#define NG   4
#define CPG  32
#define BPG  8
#define JPC  16          // j values per CTA
#define GROWS 48         // rows per CTA = JPC * 3 gates
#define WP   516         // padded row stride (floats) for w_sm
#define HP   516         // padded row stride for h_sm

// ---------------- scratch (device globals; no allocations allowed) ----------
__device__ float g_fc[BB*HID];                 // relu(z @ fc_w^T + fc_b)
__device__ float g_gx[(size_t)MTOT*G3];        // input-projection output (reused per layer)
__device__ float g_y0[(size_t)MTOT*HO];        // layer0 output
__device__ float g_y1[(size_t)MTOT*HO];        // layer1 output
__device__ float g_h2[NG][2][BPG*HO];          // per-group double-buffered hidden state
__device__ unsigned int g_flag[NG][CPG];       // per-CTA monotonic step flags

// fast gates: MUFU.EX2 + MUFU.RCP forms; rel err ~1e-6 (budget is 1e-3)
__device__ __forceinline__ float sigf(float x) {
    return __fdividef(1.0f, 1.0f + __expf(-x));
}
__device__ __forceinline__ float tanhfast(float x) {
    return 2.0f * __fdividef(1.0f, 1.0f + __expf(-2.0f * x)) - 1.0f;
}

// ---------------- FC + ReLU --------------------------------------------------
__global__ void fc_kernel(const float* __restrict__ z,
                          const float* __restrict__ fc_w,
                          const float* __restrict__ fc_b) {
    __shared__ float zs[LAT];
    int b = blockIdx.x;
    zs[threadIdx.x] = z[b*LAT + threadIdx.x];
    __syncthreads();
    for (int h = threadIdx.x; h < HID; h += blockDim.x) {
        const float4* w = (const float4*)(fc_w + (size_t)h*LAT);
        float s = fc_b[h];
        #pragma unroll 8
        for (int k = 0; k < LAT/4; k++) {
            float4 wv = w[k];
            float4 zv = *(const float4*)(zs + 4*k);
            s += wv.x*zv.x + wv.y*zv.y + wv.z*zv.z + wv.w*zv.w;
        }
        g_fc[b*HID + h] = fmaxf(s, 0.0f);
    }
}

// ---------------- Input projection GEMM (NT), software-pipelined ------------
// MODE 0: A[m,k] = g_fc[b,k] + 0.01*chord[m,k], K=HID; MODE 1/2: A=y_prev, K=HO
template<int MODE>
__global__ void __launch_bounds__(256, 2) gemm_nt(const float* __restrict__ chord,
                                                  const float* __restrict__ W,
                                                  const float* __restrict__ bias) {
    constexpr int K = (MODE == 0) ? HID : HO;
    __shared__ float As[2][8][128];
    __shared__ float Bs[2][8][132];
    const float* A = (MODE == 1) ? g_y0 : (MODE == 2) ? g_y1 : g_fc;
    int bm = blockIdx.y * 128, bn = blockIdx.x * 128;
    int tid = threadIdx.x;
    int lm = tid >> 1, lk = (tid & 1) * 4;
    int tr = (tid >> 4) * 8, tc = (tid & 15) * 8;
    float acc[8][8] = {};

    // tile loaders (global -> regs)
    auto loadA = [&](int k0) -> float4 {
        if (MODE == 0) {
            int m = bm + lm;
            float4 f = *(const float4*)(g_fc + (size_t)(m >> 9)*HID + k0 + lk);
            float4 c = *(const float4*)(chord + (size_t)m*HID + k0 + lk);
            return make_float4(f.x + 0.01f*c.x, f.y + 0.01f*c.y,
                               f.z + 0.01f*c.z, f.w + 0.01f*c.w);
        } else {
            return *(const float4*)(A + (size_t)(bm + lm)*K + k0 + lk);
        }
    };

    // prologue: tile 0 -> smem[0]
    {
        float4 av = loadA(0);
        float4 bv = *(const float4*)(W + (size_t)(bn + lm)*K + lk);
        As[0][lk+0][lm] = av.x; As[0][lk+1][lm] = av.y;
        As[0][lk+2][lm] = av.z; As[0][lk+3][lm] = av.w;
        Bs[0][lk+0][lm] = bv.x; Bs[0][lk+1][lm] = bv.y;
        Bs[0][lk+2][lm] = bv.z; Bs[0][lk+3][lm] = bv.w;
    }
    int buf = 0;
    for (int k0 = 0; k0 < K; k0 += 8) {
        __syncthreads();            // smem[buf] ready; smem[buf^1] free
        float4 na, nb;
        const bool more = (k0 + 8 < K);
        if (more) {
            na = loadA(k0 + 8);
            nb = *(const float4*)(W + (size_t)(bn + lm)*K + k0 + 8 + lk);
        }
        #pragma unroll
        for (int kk = 0; kk < 8; kk++) {
            float ar[8], br[8];
            *(float4*)&ar[0] = *(const float4*)&As[buf][kk][tr];
            *(float4*)&ar[4] = *(const float4*)&As[buf][kk][tr+4];
            *(float4*)&br[0] = *(const float4*)&Bs[buf][kk][tc];
            *(float4*)&br[4] = *(const float4*)&Bs[buf][kk][tc+4];
            #pragma unroll
            for (int i = 0; i < 8; i++)
                #pragma unroll
                for (int j = 0; j < 8; j++)
                    acc[i][j] += ar[i]*br[j];
        }
        if (more) {
            int nb2 = buf ^ 1;
            As[nb2][lk+0][lm] = na.x; As[nb2][lk+1][lm] = na.y;
            As[nb2][lk+2][lm] = na.z; As[nb2][lk+3][lm] = na.w;
            Bs[nb2][lk+0][lm] = nb.x; Bs[nb2][lk+1][lm] = nb.y;
            Bs[nb2][lk+2][lm] = nb.z; Bs[nb2][lk+3][lm] = nb.w;
        }
        buf ^= 1;
    }
    for (int i = 0; i < 8; i++) {
        int row = bm + tr + i;
        float* cp = g_gx + (size_t)row*G3 + bn + tc;
        const float* bp = bias + bn + tc;
        #pragma unroll
        for (int j = 0; j < 8; j++) cp[j] = acc[i][j] + bp[j];
    }
}

// ---------------- Persistent GRU layer ---------------------------------------
// 4 groups x 32 CTAs; atomic-free flag barrier (release store + acquire polls),
// gx(t+1) prefetch overlapped with the flag wait, MUFU-based gate math.
__global__ void __launch_bounds__(256) gru2(const float* __restrict__ whh,
                                            const float* __restrict__ bhh,
                                            float* __restrict__ dout,
                                            const int* __restrict__ seq_lens,
                                            int dst_mode) {
    extern __shared__ float sm[];
    float* w_sm  = sm;                       // GROWS * WP
    float* h_sm  = w_sm + GROWS*WP;          // BPG * HP
    float* red   = h_sm + BPG*HP;            // 32 * 8 * GROWS
    float* gh_sm = red + 32*8*GROWS;         // GROWS * 9
    float* bh_sm = gh_sm + GROWS*9;          // GROWS

    float* y = (dst_mode == 0) ? g_y0 : (dst_mode == 1) ? g_y1 : dout;

    int tid = threadIdx.x;
    int grp = blockIdx.x >> 5;
    int cig = blockIdx.x & 31;
    int jbase = cig * JPC;

    // monotonic flag base (all CTAs of a group agree: each launch does exactly
    // TT-1 uniform increments, so all flags are equal at launch entry)
    unsigned int base;
    asm volatile("ld.relaxed.gpu.u32 %0, [%1];" : "=r"(base)
                 : "l"(&g_flag[grp][cig]) : "memory");

    // stage this CTA's 48 w_hh rows (row gl = gate*16 + jj)
    for (int i = tid; i < GROWS*HO; i += 256) {
        int gl = i >> 9, k = i & (HO-1);
        int gate = gl >> 4, jj = gl & 15;
        w_sm[gl*WP + k] = whh[(size_t)(gate*HO + jbase + jj)*HO + k];
    }
    if (tid < GROWS) bh_sm[tid] = bhh[(tid >> 4)*HO + jbase + (tid & 15)];
    // zero h(0) in smem
    for (int i = tid; i < BPG*HO; i += 256)
        h_sm[(i >> 9)*HP + (i & (HO-1))] = 0.0f;

    const int ks = tid >> 3;        // k-slice 0..31 (16 k each)
    const int rg = tid & 7;         // row group 0..7
    const int k0 = ks * 16;
    const int gjj = tid & 15, gb = tid >> 4;     // gate-math coords (tid<128)
    const int b_glob = grp*BPG + gb;
    int slen = TT;
    if (dst_mode == 2 && tid < 128) slen = seq_lens[b_glob];

    // prefetch gx(0)
    float gxr = 0.f, gxz = 0.f, gxn = 0.f;
    if (tid < 128) {
        size_t bse = (size_t)b_glob*TT*G3 + jbase + gjj;
        gxr = g_gx[bse];
        gxz = g_gx[bse + HO];
        gxn = g_gx[bse + 2*HO];
    }
    __syncthreads();

    for (int t = 0; t < TT; t++) {
        // ---- GEMV partials: 6 rows x 8 batches, 16 k per thread ----
        float acc[6][8];
        #pragma unroll
        for (int u = 0; u < 6; u++)
            #pragma unroll
            for (int v = 0; v < 8; v++) acc[u][v] = 0.0f;

        #pragma unroll
        for (int kc = 0; kc < 16; kc += 4) {
            float4 w4[6];
            #pragma unroll
            for (int u = 0; u < 6; u++)
                w4[u] = *(const float4*)(w_sm + (rg + 8*u)*WP + k0 + kc);
            #pragma unroll
            for (int v = 0; v < 8; v++) {
                float4 h4 = *(const float4*)(h_sm + v*HP + k0 + kc);
                #pragma unroll
                for (int u = 0; u < 6; u++) {
                    acc[u][v] += w4[u].x*h4.x + w4[u].y*h4.y
                               + w4[u].z*h4.z + w4[u].w*h4.w;
                }
            }
        }
        #pragma unroll
        for (int u = 0; u < 6; u++)
            #pragma unroll
            for (int v = 0; v < 8; v++)
                red[(ks*8 + rg)*GROWS + u*8 + v] = acc[u][v];
        __syncthreads();

        // ---- reduce 32 k-slices -> gh_sm (+bias) ----
        for (int o = tid; o < 8*GROWS; o += 256) {
            int pos = o / GROWS, idx = o - pos*GROWS;   // pos = rg
            float s = 0.0f;
            #pragma unroll 8
            for (int ksi = 0; ksi < 32; ksi++)
                s += red[(ksi*8 + pos)*GROWS + idx];
            int u = idx >> 3, v = idx & 7;
            int gl = pos + 8*u;
            gh_sm[gl*9 + v] = s + bh_sm[gl];
        }
        __syncthreads();

        // ---- gate math: 16 j x 8 b = 128 outputs ----
        if (tid < 128) {
            float ghr = gh_sm[(     gjj)*9 + gb];
            float ghz = gh_sm[(16 + gjj)*9 + gb];
            float ghn = gh_sm[(32 + gjj)*9 + gb];
            float r  = sigf(gxr + ghr);
            float zg = sigf(gxz + ghz);
            float n  = tanhfast(gxn + r*ghn);
            float hp = h_sm[gb*HP + jbase + gjj];
            float hn2 = (1.0f - zg)*n + zg*hp;
            g_h2[grp][(t + 1) & 1][gb*HO + jbase + gjj] = hn2;   // publish first
            float yv = (t < slen) ? hn2 : 0.0f;
            y[((size_t)b_glob*TT + t)*HO + jbase + gjj] = yv;
        }
        __syncthreads();                     // all h stores done (CTA-wide)

        if (t < TT - 1) {
            // arrive: release store of this CTA's flag
            if (tid == 0) {
                asm volatile("st.release.gpu.u32 [%0], %1;"
                             :: "l"(&g_flag[grp][cig]),
                                "r"(base + (unsigned)(t + 1)) : "memory");
            }
            // overlap: prefetch gx(t+1) while the group converges
            if (tid < 128) {
                size_t bse = ((size_t)b_glob*TT + (t + 1))*G3 + jbase + gjj;
                gxr = g_gx[bse];
                gxz = g_gx[bse + HO];
                gxn = g_gx[bse + 2*HO];
            }
            // wait: warp 0 polls all 32 flags in parallel (acquire loads)
            if (tid < 32) {
                const unsigned tgt = base + (unsigned)(t + 1);
                unsigned v;
                do {
                    asm volatile("ld.acquire.gpu.u32 %0, [%1];" : "=r"(v)
                                 : "l"(&g_flag[grp][tid]) : "memory");
                } while (__ballot_sync(0xffffffffu, v < tgt));
            }
            __syncthreads();                 // acquire propagates CTA-wide
            // stage h(t+1): coalesced float4 copy
            const float* hb = g_h2[grp][(t + 1) & 1];
            for (int i = tid*4; i < BPG*HO; i += 1024) {
                float4 hv = *(const float4*)(hb + i);
                *(float4*)(h_sm + (i >> 9)*HP + (i & (HO-1))) = hv;
            }
            __syncthreads();
        }
    }
}

// ---------------- launch ----------------------------------------------------
#define GRU_SMEM ((GROWS*WP + BPG*HP + 32*8*GROWS + GROWS*9 + GROWS) * 4)

extern "C" void kernel_launch(void* const* d_in, const int* in_sizes, int n_in,
                              void* d_out, int out_size) {
    const float* z     = (const float*)d_in[0];
    const int*   seq   = (const int*)  d_in[1];
    const float* chord = (const float*)d_in[2];
    const float* fc_w  = (const float*)d_in[3];
    const float* fc_b  = (const float*)d_in[4];
    const float* w_ih0 = (const float*)d_in[5];
    const float* w_hh0 = (const float*)d_in[6];
    const float* b_ih0 = (const float*)d_in[7];
    const float* b_hh0 = (const float*)d_in[8];
    const float* w_ih1 = (const float*)d_in[9];
    const float* w_hh1 = (const float*)d_in[10];
    const float* b_ih1 = (const float*)d_in[11];
    const float* b_hh1 = (const float*)d_in[12];
    const float* w_ih2 = (const float*)d_in[13];
    const float* w_hh2 = (const float*)d_in[14];
    const float* b_ih2 = (const float*)d_in[15];
    const float* b_hh2 = (const float*)d_in[16];
    float* out = (float*)d_out;

    cudaFuncSetAttribute(gru2, cudaFuncAttributeMaxDynamicSharedMemorySize, GRU_SMEM);

    dim3 ggrid(G3/128, MTOT/128);   // (12, 128)

    fc_kernel<<<BB, LAT>>>(z, fc_w, fc_b);

    gemm_nt<0><<<ggrid, 256>>>(chord, w_ih0, b_ih0);
    gru2<<<NG*CPG, 256, GRU_SMEM>>>(w_hh0, b_hh0, nullptr, seq, 0);

    gemm_nt<1><<<ggrid, 256>>>(nullptr, w_ih1, b_ih1);
    gru2<<<NG*CPG, 256, GRU_SMEM>>>(w_hh1, b_hh1, nullptr, seq, 1);

    gemm_nt<2><<<ggrid, 256>>>(nullptr, w_ih2, b_ih2);
    gru2<<<NG*CPG, 256, GRU_SMEM>>>(w_hh2, b_hh2, out, seq, 2);
}

// round 8
// speedup vs baseline: 1.1340x; 1.1340x over previous
#include <cuda_runtime.h>
#include <math.h>

#define BB   32
#define TT   512
#define LAT  256
#define HID  1024
#define HO   512
#define G3   1536
#define MTOT (BB*TT)

// GRU partitioning: 4 independent groups x 8 batches, 32 CTAs per group.
#define NG   4
#define CPG  32
#define BPG  8
#define JPC  16          // j values per CTA
#define GROWS 48         // rows per CTA = JPC * 3 gates (24 row-pairs)
#define NPAIR 24
#define WPP  1028        // floats per row-pair in w2 (512*2 + 4 pad; /4 == 1 mod 8)
#define HP   516         // padded row stride for h_sm (b-major)

// ---------------- scratch (device globals; no allocations allowed) ----------
__device__ float g_fc[BB*HID];
__device__ float g_gx[(size_t)MTOT*G3];
__device__ float g_y0[(size_t)MTOT*HO];
__device__ float g_y1[(size_t)MTOT*HO];
__device__ float g_h2[NG][2][BPG*HO];
__device__ unsigned int g_cnt2[NG];
__device__ volatile unsigned int g_gen2[NG];

// fast gates (MUFU): rel err ~1e-6, budget 1e-3
__device__ __forceinline__ float sigf(float x) {
    return __fdividef(1.0f, 1.0f + __expf(-x));
}
__device__ __forceinline__ float tanhfast(float x) {
    return 2.0f * __fdividef(1.0f, 1.0f + __expf(-2.0f * x)) - 1.0f;
}

// packed fp32 FMA (sm_100+): d.lo = a.lo*b.lo + c.lo, d.hi likewise
__device__ __forceinline__ void ffma2(unsigned long long& acc,
                                      unsigned long long a, unsigned long long b) {
    asm("fma.rn.f32x2 %0, %1, %2, %0;" : "+l"(acc) : "l"(a), "l"(b));
}
__device__ __forceinline__ unsigned long long dup2(float x) {
    unsigned long long r;
    unsigned u = __float_as_uint(x);
    asm("mov.b64 %0, {%1, %1};" : "=l"(r) : "r"(u));
    return r;
}
__device__ __forceinline__ float2 unpack2(unsigned long long v) {
    float2 f;
    f.x = __uint_as_float((unsigned)(v & 0xffffffffull));
    f.y = __uint_as_float((unsigned)(v >> 32));
    return f;
}

// Sense-reversing barrier over the CPG CTAs of one group (atomic counting).
__device__ __forceinline__ void group_barrier(int grp) {
    __syncthreads();
    if (threadIdx.x == 0) {
        __threadfence();
        unsigned int gen = g_gen2[grp];
        if (atomicAdd(&g_cnt2[grp], 1u) == CPG - 1u) {
            g_cnt2[grp] = 0u;
            __threadfence();
            g_gen2[grp] = gen + 1u;
        } else {
            while (g_gen2[grp] == gen) { }
        }
        __threadfence();
    }
    __syncthreads();
}

// ---------------- FC + ReLU --------------------------------------------------
__global__ void fc_kernel(const float* __restrict__ z,
                          const float* __restrict__ fc_w,
                          const float* __restrict__ fc_b) {
    __shared__ float zs[LAT];
    int b = blockIdx.x;
    zs[threadIdx.x] = z[b*LAT + threadIdx.x];
    __syncthreads();
    for (int h = threadIdx.x; h < HID; h += blockDim.x) {
        const float4* w = (const float4*)(fc_w + (size_t)h*LAT);
        float s = fc_b[h];
        #pragma unroll 8
        for (int k = 0; k < LAT/4; k++) {
            float4 wv = w[k];
            float4 zv = *(const float4*)(zs + 4*k);
            s += wv.x*zv.x + wv.y*zv.y + wv.z*zv.z + wv.w*zv.w;
        }
        g_fc[b*HID + h] = fmaxf(s, 0.0f);
    }
}

// ---------------- Input projection GEMM (NT), pipelined + FFMA2 -------------
// n-pairs packed straight out of Bs (n-contiguous); A dup'd per element.
template<int MODE>
__global__ void __launch_bounds__(256, 2) gemm_nt(const float* __restrict__ chord,
                                                  const float* __restrict__ W,
                                                  const float* __restrict__ bias) {
    constexpr int K = (MODE == 0) ? HID : HO;
    __shared__ float As[2][8][128];
    __shared__ float Bs[2][8][132];
    const float* A = (MODE == 1) ? g_y0 : (MODE == 2) ? g_y1 : g_fc;
    int bm = blockIdx.y * 128, bn = blockIdx.x * 128;
    int tid = threadIdx.x;
    int lm = tid >> 1, lk = (tid & 1) * 4;
    int tr = (tid >> 4) * 8, tc = (tid & 15) * 8;
    unsigned long long acc2[8][4];
    #pragma unroll
    for (int i = 0; i < 8; i++)
        #pragma unroll
        for (int j = 0; j < 4; j++) acc2[i][j] = 0ull;

    auto loadA = [&](int k0) -> float4 {
        if (MODE == 0) {
            int m = bm + lm;
            float4 f = *(const float4*)(g_fc + (size_t)(m >> 9)*HID + k0 + lk);
            float4 c = *(const float4*)(chord + (size_t)m*HID + k0 + lk);
            return make_float4(f.x + 0.01f*c.x, f.y + 0.01f*c.y,
                               f.z + 0.01f*c.z, f.w + 0.01f*c.w);
        } else {
            return *(const float4*)(A + (size_t)(bm + lm)*K + k0 + lk);
        }
    };

    {   // prologue: tile 0 -> smem[0]
        float4 av = loadA(0);
        float4 bv = *(const float4*)(W + (size_t)(bn + lm)*K + lk);
        As[0][lk+0][lm] = av.x; As[0][lk+1][lm] = av.y;
        As[0][lk+2][lm] = av.z; As[0][lk+3][lm] = av.w;
        Bs[0][lk+0][lm] = bv.x; Bs[0][lk+1][lm] = bv.y;
        Bs[0][lk+2][lm] = bv.z; Bs[0][lk+3][lm] = bv.w;
    }
    int buf = 0;
    for (int k0 = 0; k0 < K; k0 += 8) {
        __syncthreads();
        float4 na, nb;
        const bool more = (k0 + 8 < K);
        if (more) {
            na = loadA(k0 + 8);
            nb = *(const float4*)(W + (size_t)(bn + lm)*K + k0 + 8 + lk);
        }
        #pragma unroll
        for (int kk = 0; kk < 8; kk++) {
            float ar[8];
            *(float4*)&ar[0] = *(const float4*)&As[buf][kk][tr];
            *(float4*)&ar[4] = *(const float4*)&As[buf][kk][tr+4];
            ulonglong2 b0 = *(const ulonglong2*)&Bs[buf][kk][tc];
            ulonglong2 b1 = *(const ulonglong2*)&Bs[buf][kk][tc+4];
            unsigned long long bd0 = b0.x, bd1 = b0.y, bd2 = b1.x, bd3 = b1.y;
            #pragma unroll
            for (int i = 0; i < 8; i++) {
                unsigned long long ad = dup2(ar[i]);
                ffma2(acc2[i][0], ad, bd0);
                ffma2(acc2[i][1], ad, bd1);
                ffma2(acc2[i][2], ad, bd2);
                ffma2(acc2[i][3], ad, bd3);
            }
        }
        if (more) {
            int nb2 = buf ^ 1;
            As[nb2][lk+0][lm] = na.x; As[nb2][lk+1][lm] = na.y;
            As[nb2][lk+2][lm] = na.z; As[nb2][lk+3][lm] = na.w;
            Bs[nb2][lk+0][lm] = nb.x; Bs[nb2][lk+1][lm] = nb.y;
            Bs[nb2][lk+2][lm] = nb.z; Bs[nb2][lk+3][lm] = nb.w;
        }
        buf ^= 1;
    }
    for (int i = 0; i < 8; i++) {
        int row = bm + tr + i;
        float* cp = g_gx + (size_t)row*G3 + bn + tc;
        const float* bp = bias + bn + tc;
        #pragma unroll
        for (int jp = 0; jp < 4; jp++) {
            float2 f = unpack2(acc2[i][jp]);
            cp[2*jp]     = f.x + bp[2*jp];
            cp[2*jp + 1] = f.y + bp[2*jp + 1];
        }
    }
}

// ---------------- Persistent GRU layer ---------------------------------------
// 4 groups x 32 CTAs (atomic barrier). CTA owns 16 j (48 rows = 24 row-pairs).
// w2 smem holds row-pairs interleaved: w2[p][k][c], c selects row rg+16t+8c.
// GEMV: thread = (ks 0..31, rg 0..7); k set = ks*4 + kc*128 + {0..3}
// (interleaved k-slices -> conflict-free h broadcasts). FFMA2 over row-pairs:
// acc2[t][v] (lo=row rg+16t, hi=row rg+16t+8), b-operand = dup(h[v][k]).
__global__ void __launch_bounds__(256) gru2(const float* __restrict__ whh,
                                            const float* __restrict__ bhh,
                                            float* __restrict__ dout,
                                            const int* __restrict__ seq_lens,
                                            int dst_mode) {
    extern __shared__ float sm[];
    float* w2_sm = sm;                       // NPAIR * WPP   = 24672
    float* h_sm  = w2_sm + NPAIR*WPP;        // BPG * HP      =  4128
    float* red   = h_sm + BPG*HP;            // 32 * 8 * 48   = 12288
    float* gh_sm = red + 32*8*GROWS;         // 48 * 9        =   432
    float* bh_sm = gh_sm + GROWS*9;          // 48

    float* y = (dst_mode == 0) ? g_y0 : (dst_mode == 1) ? g_y1 : dout;

    int tid = threadIdx.x;
    int grp = blockIdx.x >> 5;
    int cig = blockIdx.x & 31;
    int jbase = cig * JPC;

    // stage w2: pair p = t*8 + rg; element [p][k][c] = whh row (rg+16t+8c)
    for (int i = tid; i < NPAIR*1024; i += 256) {
        int p = i >> 10;
        int r = i & 1023;
        int k = r >> 1, c = r & 1;
        int gl = (p & 7) + 16*(p >> 3) + 8*c;
        int gate = gl >> 4, jj = gl & 15;
        w2_sm[(size_t)p*WPP + r] = whh[(size_t)(gate*HO + jbase + jj)*HO + k];
    }
    if (tid < GROWS) bh_sm[tid] = bhh[(tid >> 4)*HO + jbase + (tid & 15)];

    const int ks = tid >> 3;        // k-slice 0..31 (interleaved 4-k chunks)
    const int rg = tid & 7;         // row group 0..7
    const int gjj = tid & 15, gb = tid >> 4;     // gate-math coords (tid<128)
    const int b_glob = grp*BPG + gb;
    int slen = TT;
    if (dst_mode == 2 && tid < 128) slen = seq_lens[b_glob];
    __syncthreads();

    for (int t = 0; t < TT; t++) {
        // ---- stage h(t) for this group's 8 batches (b-major) ----
        if (t == 0) {
            for (int i = tid; i < BPG*HO; i += 256)
                h_sm[(i >> 9)*HP + (i & (HO-1))] = 0.0f;
        } else {
            const float* hb = g_h2[grp][t & 1];
            for (int i = tid*4; i < BPG*HO; i += 1024) {
                float4 v = *(const float4*)(hb + i);
                *(float4*)(h_sm + (i >> 9)*HP + (i & (HO-1))) = v;
            }
        }
        __syncthreads();

        // ---- prefetch gx (L2 latency overlaps the GEMV) ----
        float gxr = 0.f, gxz = 0.f, gxn = 0.f;
        if (tid < 128) {
            size_t bse = ((size_t)b_glob*TT + t)*G3 + jbase + gjj;
            gxr = g_gx[bse];
            gxz = g_gx[bse + HO];
            gxn = g_gx[bse + 2*HO];
        }

        // ---- GEMV partials: 3 row-pairs x 8 batches, 16 k per thread ----
        unsigned long long acc2[3][8];
        #pragma unroll
        for (int u = 0; u < 3; u++)
            #pragma unroll
            for (int v = 0; v < 8; v++) acc2[u][v] = 0ull;

        #pragma unroll
        for (int kc = 0; kc < 4; kc++) {
            int kb = ks*4 + kc*128;
            ulonglong2 wa[3], wb[3];
            #pragma unroll
            for (int u = 0; u < 3; u++) {
                const float* wp = w2_sm + (size_t)(u*8 + rg)*WPP + kb*2;
                wa[u] = *(const ulonglong2*)(wp);       // k pairs kb, kb+1
                wb[u] = *(const ulonglong2*)(wp + 4);   // k pairs kb+2, kb+3
            }
            #pragma unroll
            for (int v = 0; v < 8; v++) {
                float4 hv = *(const float4*)(h_sm + v*HP + kb);
                unsigned long long d0 = dup2(hv.x), d1 = dup2(hv.y);
                unsigned long long d2 = dup2(hv.z), d3 = dup2(hv.w);
                #pragma unroll
                for (int u = 0; u < 3; u++) {
                    ffma2(acc2[u][v], wa[u].x, d0);
                    ffma2(acc2[u][v], wa[u].y, d1);
                    ffma2(acc2[u][v], wb[u].x, d2);
                    ffma2(acc2[u][v], wb[u].y, d3);
                }
            }
        }
        // unpack: lo -> logical u=2t (row rg+16t), hi -> u=2t+1 (row rg+16t+8)
        #pragma unroll
        for (int u = 0; u < 3; u++)
            #pragma unroll
            for (int v = 0; v < 8; v++) {
                float2 f = unpack2(acc2[u][v]);
                red[(ks*8 + rg)*GROWS + (2*u + 0)*8 + v] = f.x;
                red[(ks*8 + rg)*GROWS + (2*u + 1)*8 + v] = f.y;
            }
        __syncthreads();

        // ---- reduce 32 k-slices -> gh_sm (+bias) ----
        for (int o = tid; o < 8*GROWS; o += 256) {
            int pos = o / GROWS, idx = o - pos*GROWS;   // pos = rg
            float s = 0.0f;
            #pragma unroll 8
            for (int ksi = 0; ksi < 32; ksi++)
                s += red[(ksi*8 + pos)*GROWS + idx];
            int u = idx >> 3, v = idx & 7;
            int gl = pos + 8*u;
            gh_sm[gl*9 + v] = s + bh_sm[gl];
        }
        __syncthreads();

        // ---- gate math: 16 j x 8 b = 128 outputs ----
        if (tid < 128) {
            float ghr = gh_sm[(     gjj)*9 + gb];
            float ghz = gh_sm[(16 + gjj)*9 + gb];
            float ghn = gh_sm[(32 + gjj)*9 + gb];
            float r  = sigf(gxr + ghr);
            float zg = sigf(gxz + ghz);
            float n  = tanhfast(gxn + r*ghn);
            float hp = h_sm[gb*HP + jbase + gjj];
            float hn2 = (1.0f - zg)*n + zg*hp;
            g_h2[grp][(t + 1) & 1][gb*HO + jbase + gjj] = hn2;
            float yv = (t < slen) ? hn2 : 0.0f;
            y[((size_t)b_glob*TT + t)*HO + jbase + gjj] = yv;
        }

        if (t < TT - 1) group_barrier(grp);
    }
}

// ---------------- launch ----------------------------------------------------
#define GRU_SMEM ((NPAIR*WPP + BPG*HP + 32*8*GROWS + GROWS*9 + GROWS) * 4)

extern "C" void kernel_launch(void* const* d_in, const int* in_sizes, int n_in,
                              void* d_out, int out_size) {
    const float* z     = (const float*)d_in[0];
    const int*   seq   = (const int*)  d_in[1];
    const float* chord = (const float*)d_in[2];
    const float* fc_w  = (const float*)d_in[3];
    const float* fc_b  = (const float*)d_in[4];
    const float* w_ih0 = (const float*)d_in[5];
    const float* w_hh0 = (const float*)d_in[6];
    const float* b_ih0 = (const float*)d_in[7];
    const float* b_hh0 = (const float*)d_in[8];
    const float* w_ih1 = (const float*)d_in[9];
    const float* w_hh1 = (const float*)d_in[10];
    const float* b_ih1 = (const float*)d_in[11];
    const float* b_hh1 = (const float*)d_in[12];
    const float* w_ih2 = (const float*)d_in[13];
    const float* w_hh2 = (const float*)d_in[14];
    const float* b_ih2 = (const float*)d_in[15];
    const float* b_hh2 = (const float*)d_in[16];
    float* out = (float*)d_out;

    cudaFuncSetAttribute(gru2, cudaFuncAttributeMaxDynamicSharedMemorySize, GRU_SMEM);

    dim3 ggrid(G3/128, MTOT/128);   // (12, 128)

    fc_kernel<<<BB, LAT>>>(z, fc_w, fc_b);

    gemm_nt<0><<<ggrid, 256>>>(chord, w_ih0, b_ih0);
    gru2<<<NG*CPG, 256, GRU_SMEM>>>(w_hh0, b_hh0, nullptr, seq, 0);

    gemm_nt<1><<<ggrid, 256>>>(nullptr, w_ih1, b_ih1);
    gru2<<<NG*CPG, 256, GRU_SMEM>>>(w_hh1, b_hh1, nullptr, seq, 1);

    gemm_nt<2><<<ggrid, 256>>>(nullptr, w_ih2, b_ih2);
    gru2<<<NG*CPG, 256, GRU_SMEM>>>(w_hh2, b_hh2, out, seq, 2);
}

// round 9
// speedup vs baseline: 1.1957x; 1.0544x over previous
#include <cuda_runtime.h>
#include <cuda_bf16.h>
#include <mma.h>
#include <math.h>

using namespace nvcuda;

#define BB   32
#define TT   512
#define LAT  256
#define HID  1024
#define HO   512
#define G3   1536
#define MTOT (BB*TT)

// GRU partitioning: 4 independent groups x 8 batches, 32 CTAs per group.
#define NG   4
#define CPG  32
#define BPG  8
#define JPC  16          // j values per CTA
#define GROWS 48         // rows per CTA = JPC * 3 gates
#define WP   516         // padded row stride (floats) for w_sm
#define HP   516         // padded row stride for h_sm
#define RSTR 52          // red slice stride (floats): (8ks+rg)*52 bank-spread

#define GW_LDA 24        // bf16 elems per smem tile row (48B: conflict-benign, 16B-aligned)

// ---------------- scratch (device globals; no allocations allowed) ----------
__device__ float g_fc[BB*HID];
__device__ float g_gx[(size_t)MTOT*G3];
__device__ float g_y0[(size_t)MTOT*HO];
__device__ float g_y1[(size_t)MTOT*HO];
__device__ float g_h2[NG][2][BPG*HO];
__device__ unsigned int g_cnt2[NG];
__device__ unsigned int g_gen2[NG];

// fast gates (MUFU): rel err ~1e-6, budget 1e-3
__device__ __forceinline__ float sigf(float x) {
    return __fdividef(1.0f, 1.0f + __expf(-x));
}
__device__ __forceinline__ float tanhfast(float x) {
    return 2.0f * __fdividef(1.0f, 1.0f + __expf(-2.0f * x)) - 1.0f;
}

// ---------------- FC + ReLU --------------------------------------------------
__global__ void fc_kernel(const float* __restrict__ z,
                          const float* __restrict__ fc_w,
                          const float* __restrict__ fc_b) {
    __shared__ float zs[LAT];
    int b = blockIdx.x;
    zs[threadIdx.x] = z[b*LAT + threadIdx.x];
    __syncthreads();
    for (int h = threadIdx.x; h < HID; h += blockDim.x) {
        const float4* w = (const float4*)(fc_w + (size_t)h*LAT);
        float s = fc_b[h];
        #pragma unroll 8
        for (int k = 0; k < LAT/4; k++) {
            float4 wv = w[k];
            float4 zv = *(const float4*)(zs + 4*k);
            s += wv.x*zv.x + wv.y*zv.y + wv.z*zv.z + wv.w*zv.w;
        }
        g_fc[b*HID + h] = fmaxf(s, 0.0f);
    }
}

// ---------------- Input projection GEMM via split-bf16 wmma ------------------
// D = A @ W^T + bias. A split into bf16 hi/lo (a = ah + al), same for W.
// D = ah*bh + ah*bl + al*bh (al*bl dropped, ~2^-18 relative). fp32 accumulate.
// Block tile 128m x 128n, k-step 16, 8 warps each 32m x 64n (2x4 16x16 frags).
union BfPack { __nv_bfloat162 h2[4]; uint4 v; };

template<int MODE>
__global__ void __launch_bounds__(256) gemm_wmma(const float* __restrict__ chord,
                                                 const float* __restrict__ W,
                                                 const float* __restrict__ bias) {
    constexpr int K = (MODE == 0) ? HID : HO;
    // [buf][0=Ahi,1=Alo,2=Whi,3=Wlo][128 rows * GW_LDA]
    __shared__ __align__(16) __nv_bfloat16 tiles[2][4][128*GW_LDA];
    const float* A = (MODE == 1) ? g_y0 : (MODE == 2) ? g_y1 : g_fc;
    int bm = blockIdx.y*128, bn = blockIdx.x*128;
    int tid = threadIdx.x, lane = tid & 31, wid = tid >> 5;
    int wm = wid >> 1, wn = wid & 1;      // warp tile origin (wm*32, wn*64)
    int mrow = tid >> 1, kq = (tid & 1)*8;

    wmma::fragment<wmma::accumulator,16,16,16,float> acc[2][4];
    #pragma unroll
    for (int i = 0; i < 2; i++)
        #pragma unroll
        for (int j = 0; j < 4; j++) wmma::fill_fragment(acc[i][j], 0.0f);

    auto gload = [&](int k0, float* ra, float* rb) {
        if (MODE == 0) {
            int m = bm + mrow;
            const float* fp = g_fc + (size_t)(m >> 9)*HID + k0 + kq;
            const float* cp = chord + (size_t)m*HID + k0 + kq;
            #pragma unroll
            for (int e = 0; e < 8; e++) ra[e] = fp[e] + 0.01f*cp[e];
        } else {
            const float* ap = A + (size_t)(bm + mrow)*K + k0 + kq;
            #pragma unroll
            for (int e = 0; e < 8; e++) ra[e] = ap[e];
        }
        const float* wp = W + (size_t)(bn + mrow)*K + k0 + kq;
        #pragma unroll
        for (int e = 0; e < 8; e++) rb[e] = wp[e];
    };
    auto split_store = [&](int buf, const float* ra, const float* rb) {
        BfPack ah, al, bh, bl;
        #pragma unroll
        for (int e = 0; e < 4; e++) {
            float a0 = ra[2*e], a1 = ra[2*e+1];
            __nv_bfloat16 h0 = __float2bfloat16(a0), h1 = __float2bfloat16(a1);
            ah.h2[e] = __halves2bfloat162(h0, h1);
            al.h2[e] = __halves2bfloat162(
                __float2bfloat16(a0 - __bfloat162float(h0)),
                __float2bfloat16(a1 - __bfloat162float(h1)));
            float b0 = rb[2*e], b1 = rb[2*e+1];
            __nv_bfloat16 g0 = __float2bfloat16(b0), g1 = __float2bfloat16(b1);
            bh.h2[e] = __halves2bfloat162(g0, g1);
            bl.h2[e] = __halves2bfloat162(
                __float2bfloat16(b0 - __bfloat162float(g0)),
                __float2bfloat16(b1 - __bfloat162float(g1)));
        }
        int off = mrow*GW_LDA + kq;
        *(uint4*)&tiles[buf][0][off] = ah.v;
        *(uint4*)&tiles[buf][1][off] = al.v;
        *(uint4*)&tiles[buf][2][off] = bh.v;
        *(uint4*)&tiles[buf][3][off] = bl.v;
    };

    {   // prologue
        float ra[8], rb[8];
        gload(0, ra, rb);
        split_store(0, ra, rb);
    }
    int buf = 0;
    for (int k0 = 0; k0 < K; k0 += 16) {
        __syncthreads();
        float ra[8], rb[8];
        const bool more = (k0 + 16 < K);
        if (more) gload(k0 + 16, ra, rb);

        wmma::fragment<wmma::matrix_a,16,16,16,__nv_bfloat16,wmma::row_major> fa_h[2], fa_l[2];
        wmma::fragment<wmma::matrix_b,16,16,16,__nv_bfloat16,wmma::col_major> fb_h[4], fb_l[4];
        #pragma unroll
        for (int i = 0; i < 2; i++) {
            wmma::load_matrix_sync(fa_h[i], &tiles[buf][0][(wm*32 + i*16)*GW_LDA], GW_LDA);
            wmma::load_matrix_sync(fa_l[i], &tiles[buf][1][(wm*32 + i*16)*GW_LDA], GW_LDA);
        }
        #pragma unroll
        for (int j = 0; j < 4; j++) {
            wmma::load_matrix_sync(fb_h[j], &tiles[buf][2][(wn*64 + j*16)*GW_LDA], GW_LDA);
            wmma::load_matrix_sync(fb_l[j], &tiles[buf][3][(wn*64 + j*16)*GW_LDA], GW_LDA);
        }
        #pragma unroll
        for (int i = 0; i < 2; i++)
            #pragma unroll
            for (int j = 0; j < 4; j++) {
                wmma::mma_sync(acc[i][j], fa_h[i], fb_h[j], acc[i][j]);
                wmma::mma_sync(acc[i][j], fa_h[i], fb_l[j], acc[i][j]);
                wmma::mma_sync(acc[i][j], fa_l[i], fb_h[j], acc[i][j]);
            }
        if (more) split_store(buf ^ 1, ra, rb);
        buf ^= 1;
    }
    __syncthreads();   // tiles dead -> reuse as epilogue scratch

    float* scratch = reinterpret_cast<float*>(&tiles[0][0][0]) + wid*320;  // 16x20/warp
    #pragma unroll
    for (int i = 0; i < 2; i++)
        #pragma unroll
        for (int j = 0; j < 4; j++) {
            wmma::store_matrix_sync(scratch, acc[i][j], 20, wmma::mem_row_major);
            __syncwarp();
            int r = lane >> 1, cb = (lane & 1)*8;
            int row = bm + wm*32 + i*16 + r;
            int col = bn + wn*64 + j*16 + cb;
            float4 v0 = *(float4*)&scratch[r*20 + cb];
            float4 v1 = *(float4*)&scratch[r*20 + cb + 4];
            const float* bp = bias + col;
            float* gp = g_gx + (size_t)row*G3 + col;
            float4 o0 = make_float4(v0.x + bp[0], v0.y + bp[1], v0.z + bp[2], v0.w + bp[3]);
            float4 o1 = make_float4(v1.x + bp[4], v1.y + bp[5], v1.z + bp[6], v1.w + bp[7]);
            *(float4*)gp = o0;
            *(float4*)(gp + 4) = o1;
            __syncwarp();
        }
}

// ---------------- Persistent GRU layer ---------------------------------------
// 4 groups x 32 CTAs. Atomic-arrive + generation word; ALL 256 threads spin
// with ld.acquire (one L2 round trip to release everyone). Arrive happens
// before the y-store and gx(t+1) prefetch (overlapped with convergence).
// GEMV: scalar FMA (FFMA2 is not double-rate on B300), interleaved k-slices
// (k = ks*4 + kc*128) -> conflict-free w reads + broadcast h reads.
// Reduce fused into gate math (one fewer __syncthreads).
__global__ void __launch_bounds__(256) gru3(const float* __restrict__ whh,
                                            const float* __restrict__ bhh,
                                            float* __restrict__ dout,
                                            const int* __restrict__ seq_lens,
                                            int dst_mode) {
    extern __shared__ float sm[];
    float* w_sm  = sm;                       // GROWS * WP      = 24768
    float* h_sm  = w_sm + GROWS*WP;          // BPG * HP        =  4128
    float* red   = h_sm + BPG*HP;            // 256 * RSTR      = 13312
    float* bh_sm = red + 256*RSTR;           // GROWS

    float* y = (dst_mode == 0) ? g_y0 : (dst_mode == 1) ? g_y1 : dout;

    int tid = threadIdx.x;
    int grp = blockIdx.x >> 5;
    int cig = blockIdx.x & 31;
    int jbase = cig * JPC;

    // generation base: stable until ALL CTAs of the group arrive at step 0,
    // so every CTA reads it before it can change.
    unsigned int base;
    asm volatile("ld.relaxed.gpu.u32 %0, [%1];" : "=r"(base)
                 : "l"(&g_gen2[grp]) : "memory");

    // stage this CTA's 48 w_hh rows (row gl = gate*16 + jj)
    for (int i = tid; i < GROWS*HO; i += 256) {
        int gl = i >> 9, k = i & (HO-1);
        int gate = gl >> 4, jj = gl & 15;
        w_sm[gl*WP + k] = whh[(size_t)(gate*HO + jbase + jj)*HO + k];
    }
    if (tid < GROWS) bh_sm[tid] = bhh[(tid >> 4)*HO + jbase + (tid & 15)];
    // zero h(0)
    for (int i = tid; i < BPG*HO; i += 256)
        h_sm[(i >> 9)*HP + (i & (HO-1))] = 0.0f;

    const int ks = tid >> 3;        // k-slice 0..31 (interleaved chunks of 4)
    const int rg = tid & 7;         // row group 0..7
    const int gjj = tid & 15, gb = tid >> 4;     // gate coords (tid<128)
    const int b_glob = grp*BPG + gb;
    int slen = TT;
    if (dst_mode == 2 && tid < 128) slen = seq_lens[b_glob];

    // prefetch gx(0)
    float gxr = 0.f, gxz = 0.f, gxn = 0.f;
    if (tid < 128) {
        size_t bse = (size_t)b_glob*TT*G3 + jbase + gjj;
        gxr = g_gx[bse];
        gxz = g_gx[bse + HO];
        gxn = g_gx[bse + 2*HO];
    }
    __syncthreads();

    for (int t = 0; t < TT; t++) {
        // ---- GEMV partials: 6 rows x 8 batches, 16 k per thread ----
        float acc[6][8];
        #pragma unroll
        for (int u = 0; u < 6; u++)
            #pragma unroll
            for (int v = 0; v < 8; v++) acc[u][v] = 0.0f;

        #pragma unroll
        for (int kc = 0; kc < 4; kc++) {
            int kb = ks*4 + kc*128;
            float4 w4[6];
            #pragma unroll
            for (int u = 0; u < 6; u++)
                w4[u] = *(const float4*)(w_sm + (rg + 8*u)*WP + kb);
            #pragma unroll
            for (int v = 0; v < 8; v++) {
                float4 h4 = *(const float4*)(h_sm + v*HP + kb);
                #pragma unroll
                for (int u = 0; u < 6; u++) {
                    acc[u][v] += w4[u].x*h4.x + w4[u].y*h4.y
                               + w4[u].z*h4.z + w4[u].w*h4.w;
                }
            }
        }
        {
            float* rp = red + (ks*8 + rg)*RSTR;
            #pragma unroll
            for (int u = 0; u < 6; u++) {
                *(float4*)(rp + u*8)     = make_float4(acc[u][0], acc[u][1], acc[u][2], acc[u][3]);
                *(float4*)(rp + u*8 + 4) = make_float4(acc[u][4], acc[u][5], acc[u][6], acc[u][7]);
            }
        }
        __syncthreads();

        // ---- fused reduce + gate math (tid<128: 16 j x 8 b) ----
        float hn2 = 0.f, yv = 0.f;
        if (tid < 128) {
            float gh[3];
            #pragma unroll
            for (int g = 0; g < 3; g++) {
                int gl = g*16 + gjj;
                int rr = gl & 7, uu = gl >> 3;
                const float* rp = red + uu*8 + gb;
                float s = 0.0f;
                #pragma unroll 8
                for (int ksi = 0; ksi < 32; ksi++)
                    s += rp[(ksi*8 + rr)*RSTR];
                gh[g] = s + bh_sm[gl];
            }
            float r  = sigf(gxr + gh[0]);
            float zg = sigf(gxz + gh[1]);
            float n  = tanhfast(gxn + r*gh[2]);
            float hp = h_sm[gb*HP + jbase + gjj];
            hn2 = (1.0f - zg)*n + zg*hp;
            if (t < TT - 1)
                g_h2[grp][(t + 1) & 1][gb*HO + jbase + gjj] = hn2;
            yv = (t < slen) ? hn2 : 0.0f;
        }
        __syncthreads();                 // h stores done CTA-wide

        if (t < TT - 1) {
            const unsigned tgt = base + (unsigned)(t + 1);
            // arrive ASAP
            if (tid == 0) {
                __threadfence();
                if (atomicAdd(&g_cnt2[grp], 1u) == CPG - 1u) {
                    g_cnt2[grp] = 0u;
                    __threadfence();
                    asm volatile("st.relaxed.gpu.u32 [%0], %1;"
                                 :: "l"(&g_gen2[grp]), "r"(tgt) : "memory");
                }
            }
            // overlapped with group convergence: y store + gx(t+1) prefetch
            if (tid < 128) {
                y[((size_t)b_glob*TT + t)*HO + jbase + gjj] = yv;
                size_t bse = ((size_t)b_glob*TT + (t + 1))*G3 + jbase + gjj;
                gxr = g_gx[bse];
                gxz = g_gx[bse + HO];
                gxn = g_gx[bse + 2*HO];
            }
            // ALL threads spin: one acquire round trip releases everyone
            unsigned v;
            do {
                asm volatile("ld.acquire.gpu.u32 %0, [%1];" : "=r"(v)
                             : "l"(&g_gen2[grp]) : "memory");
            } while ((int)(v - tgt) < 0);
            // stage h(t+1)
            const float* hb = g_h2[grp][(t + 1) & 1];
            for (int i = tid*4; i < BPG*HO; i += 1024) {
                float4 hv = *(const float4*)(hb + i);
                *(float4*)(h_sm + (i >> 9)*HP + (i & (HO-1))) = hv;
            }
            __syncthreads();
        } else {
            if (tid < 128)
                y[((size_t)b_glob*TT + t)*HO + jbase + gjj] = yv;
        }
    }
}

// ---------------- launch ----------------------------------------------------
#define GRU_SMEM ((GROWS*WP + BPG*HP + 256*RSTR + GROWS) * 4)

extern "C" void kernel_launch(void* const* d_in, const int* in_sizes, int n_in,
                              void* d_out, int out_size) {
    const float* z     = (const float*)d_in[0];
    const int*   seq   = (const int*)  d_in[1];
    const float* chord = (const float*)d_in[2];
    const float* fc_w  = (const float*)d_in[3];
    const float* fc_b  = (const float*)d_in[4];
    const float* w_ih0 = (const float*)d_in[5];
    const float* w_hh0 = (const float*)d_in[6];
    const float* b_ih0 = (const float*)d_in[7];
    const float* b_hh0 = (const float*)d_in[8];
    const float* w_ih1 = (const float*)d_in[9];
    const float* w_hh1 = (const float*)d_in[10];
    const float* b_ih1 = (const float*)d_in[11];
    const float* b_hh1 = (const float*)d_in[12];
    const float* w_ih2 = (const float*)d_in[13];
    const float* w_hh2 = (const float*)d_in[14];
    const float* b_ih2 = (const float*)d_in[15];
    const float* b_hh2 = (const float*)d_in[16];
    float* out = (float*)d_out;

    cudaFuncSetAttribute(gru3, cudaFuncAttributeMaxDynamicSharedMemorySize, GRU_SMEM);

    dim3 ggrid(G3/128, MTOT/128);   // (12, 128)

    fc_kernel<<<BB, LAT>>>(z, fc_w, fc_b);

    gemm_wmma<0><<<ggrid, 256>>>(chord, w_ih0, b_ih0);
    gru3<<<NG*CPG, 256, GRU_SMEM>>>(w_hh0, b_hh0, nullptr, seq, 0);

    gemm_wmma<1><<<ggrid, 256>>>(nullptr, w_ih1, b_ih1);
    gru3<<<NG*CPG, 256, GRU_SMEM>>>(w_hh1, b_hh1, nullptr, seq, 1);

    gemm_wmma<2><<<ggrid, 256>>>(nullptr, w_ih2, b_ih2);
    gru3<<<NG*CPG, 256, GRU_SMEM>>>(w_hh2, b_hh2, out, seq, 2);
}

// round 10
// speedup vs baseline: 1.5266x; 1.2768x over previous
#include <cuda_runtime.h>
#include <cuda_bf16.h>
#include <mma.h>
#include <math.h>

using namespace nvcuda;

#define BB   32
#define TT   512
#define LAT  256
#define HID  1024
#define HO   512
#define G3   1536
#define MTOT (BB*TT)

// GRU partitioning: 4 independent groups x 8 batches, 32 CTAs per group.
#define NG   4
#define CPG  32
#define BPG  8
#define JPC  16          // j values per CTA
#define GROWS 48         // rows per CTA = JPC * 3 gates
#define HP   516         // padded row stride for h_sm (b-major)
#define RROW 10          // red row pad (floats)
#define RMT  160         // red per-(warp,mtile) stride = 16*RROW

#define GW_LDA 24        // bf16 elems per smem tile row in gemm_wmma

// ---------------- scratch (device globals; no allocations allowed) ----------
__device__ float g_fc[BB*HID];
__device__ float g_gx[(size_t)MTOT*G3];
__device__ float g_y0[(size_t)MTOT*HO];
__device__ float g_y1[(size_t)MTOT*HO];
__device__ float g_h2[NG][2][BPG*HO];
__device__ unsigned int g_cnt2[NG];
__device__ unsigned int g_gen2[NG];

// fast gates (MUFU): rel err ~1e-6, budget 1e-3
__device__ __forceinline__ float sigf(float x) {
    return __fdividef(1.0f, 1.0f + __expf(-x));
}
__device__ __forceinline__ float tanhfast(float x) {
    return 2.0f * __fdividef(1.0f, 1.0f + __expf(-2.0f * x)) - 1.0f;
}

// split a pair of fp32 into packed bf16x2 hi + lo (a = hi + lo, |lo| ~ 2^-9|a|)
__device__ __forceinline__ void split2(float x, float y, unsigned& hi, unsigned& lo) {
    __nv_bfloat16 hx = __float2bfloat16(x), hy = __float2bfloat16(y);
    __nv_bfloat16 lx = __float2bfloat16(x - __bfloat162float(hx));
    __nv_bfloat16 ly = __float2bfloat16(y - __bfloat162float(hy));
    __nv_bfloat162 h2 = __halves2bfloat162(hx, hy);
    __nv_bfloat162 l2 = __halves2bfloat162(lx, ly);
    hi = *reinterpret_cast<unsigned*>(&h2);
    lo = *reinterpret_cast<unsigned*>(&l2);
}

// mma.m16n8k16 row.col f32 += bf16 * bf16
__device__ __forceinline__ void mma_bf16(float d[4], const unsigned a[4],
                                         unsigned b0, unsigned b1) {
    asm volatile(
        "mma.sync.aligned.m16n8k16.row.col.f32.bf16.bf16.f32 "
        "{%0,%1,%2,%3}, {%4,%5,%6,%7}, {%8,%9}, {%0,%1,%2,%3};"
        : "+f"(d[0]), "+f"(d[1]), "+f"(d[2]), "+f"(d[3])
        : "r"(a[0]), "r"(a[1]), "r"(a[2]), "r"(a[3]), "r"(b0), "r"(b1));
}

// ---------------- FC + ReLU --------------------------------------------------
__global__ void fc_kernel(const float* __restrict__ z,
                          const float* __restrict__ fc_w,
                          const float* __restrict__ fc_b) {
    __shared__ float zs[LAT];
    int b = blockIdx.x;
    zs[threadIdx.x] = z[b*LAT + threadIdx.x];
    __syncthreads();
    for (int h = threadIdx.x; h < HID; h += blockDim.x) {
        const float4* w = (const float4*)(fc_w + (size_t)h*LAT);
        float s = fc_b[h];
        #pragma unroll 8
        for (int k = 0; k < LAT/4; k++) {
            float4 wv = w[k];
            float4 zv = *(const float4*)(zs + 4*k);
            s += wv.x*zv.x + wv.y*zv.y + wv.z*zv.z + wv.w*zv.w;
        }
        g_fc[b*HID + h] = fmaxf(s, 0.0f);
    }
}

// ---------------- Input projection GEMM via split-bf16 wmma (unchanged R8) ---
union BfPack { __nv_bfloat162 h2[4]; uint4 v; };

template<int MODE>
__global__ void __launch_bounds__(256) gemm_wmma(const float* __restrict__ chord,
                                                 const float* __restrict__ W,
                                                 const float* __restrict__ bias) {
    constexpr int K = (MODE == 0) ? HID : HO;
    __shared__ __align__(16) __nv_bfloat16 tiles[2][4][128*GW_LDA];
    const float* A = (MODE == 1) ? g_y0 : (MODE == 2) ? g_y1 : g_fc;
    int bm = blockIdx.y*128, bn = blockIdx.x*128;
    int tid = threadIdx.x, lane = tid & 31, wid = tid >> 5;
    int wm = wid >> 1, wn = wid & 1;
    int mrow = tid >> 1, kq = (tid & 1)*8;

    wmma::fragment<wmma::accumulator,16,16,16,float> acc[2][4];
    #pragma unroll
    for (int i = 0; i < 2; i++)
        #pragma unroll
        for (int j = 0; j < 4; j++) wmma::fill_fragment(acc[i][j], 0.0f);

    auto gload = [&](int k0, float* ra, float* rb) {
        if (MODE == 0) {
            int m = bm + mrow;
            const float* fp = g_fc + (size_t)(m >> 9)*HID + k0 + kq;
            const float* cp = chord + (size_t)m*HID + k0 + kq;
            #pragma unroll
            for (int e = 0; e < 8; e++) ra[e] = fp[e] + 0.01f*cp[e];
        } else {
            const float* ap = A + (size_t)(bm + mrow)*K + k0 + kq;
            #pragma unroll
            for (int e = 0; e < 8; e++) ra[e] = ap[e];
        }
        const float* wp = W + (size_t)(bn + mrow)*K + k0 + kq;
        #pragma unroll
        for (int e = 0; e < 8; e++) rb[e] = wp[e];
    };
    auto split_store = [&](int buf, const float* ra, const float* rb) {
        BfPack ah, al, bh, bl;
        #pragma unroll
        for (int e = 0; e < 4; e++) {
            float a0 = ra[2*e], a1 = ra[2*e+1];
            __nv_bfloat16 h0 = __float2bfloat16(a0), h1 = __float2bfloat16(a1);
            ah.h2[e] = __halves2bfloat162(h0, h1);
            al.h2[e] = __halves2bfloat162(
                __float2bfloat16(a0 - __bfloat162float(h0)),
                __float2bfloat16(a1 - __bfloat162float(h1)));
            float b0 = rb[2*e], b1 = rb[2*e+1];
            __nv_bfloat16 g0 = __float2bfloat16(b0), g1 = __float2bfloat16(b1);
            bh.h2[e] = __halves2bfloat162(g0, g1);
            bl.h2[e] = __halves2bfloat162(
                __float2bfloat16(b0 - __bfloat162float(g0)),
                __float2bfloat16(b1 - __bfloat162float(g1)));
        }
        int off = mrow*GW_LDA + kq;
        *(uint4*)&tiles[buf][0][off] = ah.v;
        *(uint4*)&tiles[buf][1][off] = al.v;
        *(uint4*)&tiles[buf][2][off] = bh.v;
        *(uint4*)&tiles[buf][3][off] = bl.v;
    };

    {   float ra[8], rb[8];
        gload(0, ra, rb);
        split_store(0, ra, rb);
    }
    int buf = 0;
    for (int k0 = 0; k0 < K; k0 += 16) {
        __syncthreads();
        float ra[8], rb[8];
        const bool more = (k0 + 16 < K);
        if (more) gload(k0 + 16, ra, rb);

        wmma::fragment<wmma::matrix_a,16,16,16,__nv_bfloat16,wmma::row_major> fa_h[2], fa_l[2];
        wmma::fragment<wmma::matrix_b,16,16,16,__nv_bfloat16,wmma::col_major> fb_h[4], fb_l[4];
        #pragma unroll
        for (int i = 0; i < 2; i++) {
            wmma::load_matrix_sync(fa_h[i], &tiles[buf][0][(wm*32 + i*16)*GW_LDA], GW_LDA);
            wmma::load_matrix_sync(fa_l[i], &tiles[buf][1][(wm*32 + i*16)*GW_LDA], GW_LDA);
        }
        #pragma unroll
        for (int j = 0; j < 4; j++) {
            wmma::load_matrix_sync(fb_h[j], &tiles[buf][2][(wn*64 + j*16)*GW_LDA], GW_LDA);
            wmma::load_matrix_sync(fb_l[j], &tiles[buf][3][(wn*64 + j*16)*GW_LDA], GW_LDA);
        }
        #pragma unroll
        for (int i = 0; i < 2; i++)
            #pragma unroll
            for (int j = 0; j < 4; j++) {
                wmma::mma_sync(acc[i][j], fa_h[i], fb_h[j], acc[i][j]);
                wmma::mma_sync(acc[i][j], fa_h[i], fb_l[j], acc[i][j]);
                wmma::mma_sync(acc[i][j], fa_l[i], fb_h[j], acc[i][j]);
            }
        if (more) split_store(buf ^ 1, ra, rb);
        buf ^= 1;
    }
    __syncthreads();

    float* scratch = reinterpret_cast<float*>(&tiles[0][0][0]) + wid*320;
    #pragma unroll
    for (int i = 0; i < 2; i++)
        #pragma unroll
        for (int j = 0; j < 4; j++) {
            wmma::store_matrix_sync(scratch, acc[i][j], 20, wmma::mem_row_major);
            __syncwarp();
            int r = lane >> 1, cb = (lane & 1)*8;
            int row = bm + wm*32 + i*16 + r;
            int col = bn + wn*64 + j*16 + cb;
            float4 v0 = *(float4*)&scratch[r*20 + cb];
            float4 v1 = *(float4*)&scratch[r*20 + cb + 4];
            const float* bp = bias + col;
            float* gp = g_gx + (size_t)row*G3 + col;
            *(float4*)gp = make_float4(v0.x + bp[0], v0.y + bp[1], v0.z + bp[2], v0.w + bp[3]);
            *(float4*)(gp + 4) = make_float4(v1.x + bp[4], v1.y + bp[5], v1.z + bp[6], v1.w + bp[7]);
            __syncwarp();
        }
}

// ---------------- Persistent GRU layer: tensor-core recurrence ---------------
// 4 groups x 32 CTAs. CTA owns 16 j (48 gate-rows = 3 m-tiles of 16).
// W slice lives in REGISTERS as mma A-fragments (split-bf16 hi/lo, loaded once):
//   awhi/awlo[m][kt4][4], m = gate, kt4 = k-subtile of this warp's k-slice.
// Per step, each warp (k-slice of 64): build B-frags from h_sm (fp32 -> hi/lo),
// issue 36 mma.m16n8k16 (3 m x 4 kt x {wh*hh, wh*hl, wl*hh}); cross-warp
// reduce via red smem (conflict-free banking), fused with gate math.
__global__ void __launch_bounds__(256) gru4(const float* __restrict__ whh,
                                            const float* __restrict__ bhh,
                                            float* __restrict__ dout,
                                            const int* __restrict__ seq_lens,
                                            int dst_mode) {
    extern __shared__ float sm[];
    float* h_sm  = sm;                       // BPG * HP   = 4128 floats
    float* red   = h_sm + BPG*HP;            // 24 * RMT   = 3840 floats
    float* bh_sm = red + 24*RMT;             // GROWS

    float* y = (dst_mode == 0) ? g_y0 : (dst_mode == 1) ? g_y1 : dout;

    int tid = threadIdx.x, lane = tid & 31, warp = tid >> 5;
    int grp = blockIdx.x >> 5;
    int cig = blockIdx.x & 31;
    int jbase = cig * JPC;

    unsigned int base;
    asm volatile("ld.relaxed.gpu.u32 %0, [%1];" : "=r"(base)
                 : "l"(&g_gen2[grp]) : "memory");

    // ---- preload W fragments into registers (one time) ----
    // A-frag m16n8k16 row-major: a0=(r,c), a1=(r+8,c), a2=(r,c+8), a3=(r+8,c+8)
    // with r = lane>>2, c = (lane&3)*2 within tile; global row = m*HO+jbase+r,
    // global col = (warp*4+kt4)*16 + c.
    unsigned awhi[3][4][4], awlo[3][4][4];
    {
        int r = lane >> 2, c = (lane & 3)*2;
        #pragma unroll
        for (int m = 0; m < 3; m++) {
            size_t row0 = (size_t)(m*HO + jbase + r)*HO;
            size_t row1 = row0 + 8*(size_t)HO;
            #pragma unroll
            for (int kt4 = 0; kt4 < 4; kt4++) {
                int kb = (warp*4 + kt4)*16 + c;
                float2 w00 = *(const float2*)(whh + row0 + kb);
                float2 w10 = *(const float2*)(whh + row1 + kb);
                float2 w01 = *(const float2*)(whh + row0 + kb + 8);
                float2 w11 = *(const float2*)(whh + row1 + kb + 8);
                split2(w00.x, w00.y, awhi[m][kt4][0], awlo[m][kt4][0]);
                split2(w10.x, w10.y, awhi[m][kt4][1], awlo[m][kt4][1]);
                split2(w01.x, w01.y, awhi[m][kt4][2], awlo[m][kt4][2]);
                split2(w11.x, w11.y, awhi[m][kt4][3], awlo[m][kt4][3]);
            }
        }
    }
    if (tid < GROWS) bh_sm[tid] = bhh[(tid >> 4)*HO + jbase + (tid & 15)];
    // zero h(0)
    for (int i = tid; i < BPG*HO; i += 256)
        h_sm[(i >> 9)*HP + (i & (HO-1))] = 0.0f;

    const int gjj = tid & 15, gb = tid >> 4;     // gate coords (tid<128)
    const int b_glob = grp*BPG + gb;
    int slen = TT;
    if (dst_mode == 2 && tid < 128) slen = seq_lens[b_glob];

    // prefetch gx(0)
    float gxr = 0.f, gxz = 0.f, gxn = 0.f;
    if (tid < 128) {
        size_t bse = (size_t)b_glob*TT*G3 + jbase + gjj;
        gxr = g_gx[bse];
        gxz = g_gx[bse + HO];
        gxn = g_gx[bse + 2*HO];
    }
    __syncthreads();

    const int bq = lane >> 2;             // B-frag batch index
    const int kc2 = (lane & 3)*2;         // B-frag k offset

    for (int t = 0; t < TT; t++) {
        // ---- tensor-core GEMV: D[m][16x8] += Wslice * h ----
        float d[3][4];
        #pragma unroll
        for (int m = 0; m < 3; m++)
            #pragma unroll
            for (int e = 0; e < 4; e++) d[m][e] = 0.0f;

        #pragma unroll
        for (int kt4 = 0; kt4 < 4; kt4++) {
            int kb = (warp*4 + kt4)*16 + kc2;
            const float* hp = h_sm + bq*HP + kb;
            float2 v0 = *(const float2*)(hp);        // h[kb], h[kb+1]
            float2 v1 = *(const float2*)(hp + 8);    // h[kb+8], h[kb+9]
            unsigned bh0, bl0, bh1, bl1;
            split2(v0.x, v0.y, bh0, bl0);
            split2(v1.x, v1.y, bh1, bl1);
            #pragma unroll
            for (int m = 0; m < 3; m++) {
                mma_bf16(d[m], awhi[m][kt4], bh0, bh1);
                mma_bf16(d[m], awhi[m][kt4], bl0, bl1);
                mma_bf16(d[m], awlo[m][kt4], bh0, bh1);
            }
        }
        // D layout: c0,c1 = D[r=lane>>2][b=(lane&3)*2 +{0,1}], c2,c3 = row+8
        #pragma unroll
        for (int m = 0; m < 3; m++) {
            float* rp = red + (warp*3 + m)*RMT + (lane>>2)*RROW + (lane&3)*2;
            *(float2*)rp        = make_float2(d[m][0], d[m][1]);
            *(float2*)(rp + 8*RROW) = make_float2(d[m][2], d[m][3]);
        }
        __syncthreads();

        // ---- fused reduce + gate math (tid<128: 16 j x 8 b) ----
        float hn2 = 0.f, yv = 0.f;
        if (tid < 128) {
            float gh[3];
            #pragma unroll
            for (int g = 0; g < 3; g++) {
                const float* rp = red + g*RMT + gjj*RROW + gb;
                float s = 0.0f;
                #pragma unroll
                for (int w = 0; w < 8; w++)
                    s += rp[w*3*RMT];
                gh[g] = s + bh_sm[g*16 + gjj];
            }
            float r  = sigf(gxr + gh[0]);
            float zg = sigf(gxz + gh[1]);
            float n  = tanhfast(gxn + r*gh[2]);
            float hp = h_sm[gb*HP + jbase + gjj];
            hn2 = (1.0f - zg)*n + zg*hp;
            if (t < TT - 1)
                g_h2[grp][(t + 1) & 1][gb*HO + jbase + gjj] = hn2;
            yv = (t < slen) ? hn2 : 0.0f;
        }
        __syncthreads();                 // h stores done CTA-wide

        if (t < TT - 1) {
            const unsigned tgt = base + (unsigned)(t + 1);
            if (tid == 0) {
                __threadfence();
                if (atomicAdd(&g_cnt2[grp], 1u) == CPG - 1u) {
                    g_cnt2[grp] = 0u;
                    __threadfence();
                    asm volatile("st.relaxed.gpu.u32 [%0], %1;"
                                 :: "l"(&g_gen2[grp]), "r"(tgt) : "memory");
                }
            }
            // overlapped with group convergence: y store + gx(t+1) prefetch
            if (tid < 128) {
                y[((size_t)b_glob*TT + t)*HO + jbase + gjj] = yv;
                size_t bse = ((size_t)b_glob*TT + (t + 1))*G3 + jbase + gjj;
                gxr = g_gx[bse];
                gxz = g_gx[bse + HO];
                gxn = g_gx[bse + 2*HO];
            }
            unsigned v;
            do {
                asm volatile("ld.acquire.gpu.u32 %0, [%1];" : "=r"(v)
                             : "l"(&g_gen2[grp]) : "memory");
            } while ((int)(v - tgt) < 0);
            // stage h(t+1)
            const float* hb = g_h2[grp][(t + 1) & 1];
            for (int i = tid*4; i < BPG*HO; i += 1024) {
                float4 hv = *(const float4*)(hb + i);
                *(float4*)(h_sm + (i >> 9)*HP + (i & (HO-1))) = hv;
            }
            __syncthreads();
        } else {
            if (tid < 128)
                y[((size_t)b_glob*TT + t)*HO + jbase + gjj] = yv;
        }
    }
}

// ---------------- launch ----------------------------------------------------
#define GRU_SMEM ((BPG*HP + 24*RMT + GROWS) * 4)

extern "C" void kernel_launch(void* const* d_in, const int* in_sizes, int n_in,
                              void* d_out, int out_size) {
    const float* z     = (const float*)d_in[0];
    const int*   seq   = (const int*)  d_in[1];
    const float* chord = (const float*)d_in[2];
    const float* fc_w  = (const float*)d_in[3];
    const float* fc_b  = (const float*)d_in[4];
    const float* w_ih0 = (const float*)d_in[5];
    const float* w_hh0 = (const float*)d_in[6];
    const float* b_ih0 = (const float*)d_in[7];
    const float* b_hh0 = (const float*)d_in[8];
    const float* w_ih1 = (const float*)d_in[9];
    const float* w_hh1 = (const float*)d_in[10];
    const float* b_ih1 = (const float*)d_in[11];
    const float* b_hh1 = (const float*)d_in[12];
    const float* w_ih2 = (const float*)d_in[13];
    const float* w_hh2 = (const float*)d_in[14];
    const float* b_ih2 = (const float*)d_in[15];
    const float* b_hh2 = (const float*)d_in[16];
    float* out = (float*)d_out;

    cudaFuncSetAttribute(gru4, cudaFuncAttributeMaxDynamicSharedMemorySize, GRU_SMEM);

    dim3 ggrid(G3/128, MTOT/128);   // (12, 128)

    fc_kernel<<<BB, LAT>>>(z, fc_w, fc_b);

    gemm_wmma<0><<<ggrid, 256>>>(chord, w_ih0, b_ih0);
    gru4<<<NG*CPG, 256, GRU_SMEM>>>(w_hh0, b_hh0, nullptr, seq, 0);

    gemm_wmma<1><<<ggrid, 256>>>(nullptr, w_ih1, b_ih1);
    gru4<<<NG*CPG, 256, GRU_SMEM>>>(w_hh1, b_hh1, nullptr, seq, 1);

    gemm_wmma<2><<<ggrid, 256>>>(nullptr, w_ih2, b_ih2);
    gru4<<<NG*CPG, 256, GRU_SMEM>>>(w_hh2, b_hh2, out, seq, 2);
}

// round 11
// speedup vs baseline: 1.8698x; 1.2248x over previous
#include <cuda_runtime.h>
#include <cuda_bf16.h>
#include <mma.h>
#include <math.h>

using namespace nvcuda;

#define BB   32
#define TT   512
#define LAT  256
#define HID  1024
#define HO   512
#define G3   1536
#define MTOT (BB*TT)

// GRU partitioning: 4 independent groups x 8 batches, 32 CTAs per group.
#define NG   4
#define CPG  32
#define BPG  8
#define JPC  16
#define GROWS 48
#define HP   516
#define RROW 10
#define RMT  160

#define GLDA 40          // bf16 elems per smem row in gemm (32 data + 8 pad = 80B)

// ---------------- scratch (device globals; no allocations allowed) ----------
__device__ float g_fc[BB*HID];
__device__ float g_gx[(size_t)MTOT*G3];
__device__ __nv_bfloat16 g_ahi[(size_t)MTOT*HID];   // A operand hi (layer0: HID; 1/2: HO stride)
__device__ __nv_bfloat16 g_alo[(size_t)MTOT*HID];   // A operand lo
__device__ __nv_bfloat16 g_whi[(size_t)G3*HID];     // W operand hi (re-split per layer)
__device__ __nv_bfloat16 g_wlo[(size_t)G3*HID];
__device__ float g_h2[NG][2][BPG*HO];
__device__ unsigned int g_cnt2[NG];
__device__ unsigned int g_gen2[NG];

// fast gates (MUFU): rel err ~1e-6, budget 1e-3
__device__ __forceinline__ float sigf(float x) {
    return __fdividef(1.0f, 1.0f + __expf(-x));
}
__device__ __forceinline__ float tanhfast(float x) {
    return 2.0f * __fdividef(1.0f, 1.0f + __expf(-2.0f * x)) - 1.0f;
}

__device__ __forceinline__ void split1(float x, __nv_bfloat16& hi, __nv_bfloat16& lo) {
    hi = __float2bfloat16(x);
    lo = __float2bfloat16(x - __bfloat162float(hi));
}
// split a pair of fp32 into packed bf16x2 hi + lo
__device__ __forceinline__ void split2(float x, float y, unsigned& hi, unsigned& lo) {
    __nv_bfloat16 hx, lx, hy, ly;
    split1(x, hx, lx); split1(y, hy, ly);
    __nv_bfloat162 h2 = __halves2bfloat162(hx, hy);
    __nv_bfloat162 l2 = __halves2bfloat162(lx, ly);
    hi = *reinterpret_cast<unsigned*>(&h2);
    lo = *reinterpret_cast<unsigned*>(&l2);
}

// mma.m16n8k16 row.col f32 += bf16 * bf16
__device__ __forceinline__ void mma_bf16(float d[4], const unsigned a[4],
                                         unsigned b0, unsigned b1) {
    asm volatile(
        "mma.sync.aligned.m16n8k16.row.col.f32.bf16.bf16.f32 "
        "{%0,%1,%2,%3}, {%4,%5,%6,%7}, {%8,%9}, {%0,%1,%2,%3};"
        : "+f"(d[0]), "+f"(d[1]), "+f"(d[2]), "+f"(d[3])
        : "r"(a[0]), "r"(a[1]), "r"(a[2]), "r"(a[3]), "r"(b0), "r"(b1));
}

// ---------------- FC + ReLU --------------------------------------------------
__global__ void fc_kernel(const float* __restrict__ z,
                          const float* __restrict__ fc_w,
                          const float* __restrict__ fc_b) {
    __shared__ float zs[LAT];
    int b = blockIdx.x;
    zs[threadIdx.x] = z[b*LAT + threadIdx.x];
    __syncthreads();
    for (int h = threadIdx.x; h < HID; h += blockDim.x) {
        const float4* w = (const float4*)(fc_w + (size_t)h*LAT);
        float s = fc_b[h];
        #pragma unroll 8
        for (int k = 0; k < LAT/4; k++) {
            float4 wv = w[k];
            float4 zv = *(const float4*)(zs + 4*k);
            s += wv.x*zv.x + wv.y*zv.y + wv.z*zv.z + wv.w*zv.w;
        }
        g_fc[b*HID + h] = fmaxf(s, 0.0f);
    }
}

// ---------------- split prepasses -------------------------------------------
// W -> hi/lo planes (n = G3*K elements)
__global__ void split_w(const float* __restrict__ W, int n) {
    int i = (blockIdx.x*256 + threadIdx.x)*4;
    if (i >= n) return;
    float4 v = *(const float4*)(W + i);
    __nv_bfloat16 h0,l0,h1,l1,h2,l2,h3,l3;
    split1(v.x,h0,l0); split1(v.y,h1,l1); split1(v.z,h2,l2); split1(v.w,h3,l3);
    *(__nv_bfloat162*)(g_whi + i)     = __halves2bfloat162(h0,h1);
    *(__nv_bfloat162*)(g_whi + i + 2) = __halves2bfloat162(h2,h3);
    *(__nv_bfloat162*)(g_wlo + i)     = __halves2bfloat162(l0,l1);
    *(__nv_bfloat162*)(g_wlo + i + 2) = __halves2bfloat162(l2,l3);
}

// layer-0 A = relu(fc)[b] + 0.01*chord -> hi/lo planes (stride HID)
__global__ void split_a0(const float* __restrict__ chord) {
    size_t i = ((size_t)blockIdx.x*256 + threadIdx.x)*4;   // < MTOT*HID
    int m = (int)(i >> 10);            // / HID
    int k = (int)(i & (HID-1));
    int b = m >> 9;                    // / TT
    float4 f = *(const float4*)(g_fc + (size_t)b*HID + k);
    float4 c = *(const float4*)(chord + i);
    float a0 = f.x + 0.01f*c.x, a1 = f.y + 0.01f*c.y;
    float a2 = f.z + 0.01f*c.z, a3 = f.w + 0.01f*c.w;
    __nv_bfloat16 h0,l0,h1,l1,h2,l2,h3,l3;
    split1(a0,h0,l0); split1(a1,h1,l1); split1(a2,h2,l2); split1(a3,h3,l3);
    *(__nv_bfloat162*)(g_ahi + i)     = __halves2bfloat162(h0,h1);
    *(__nv_bfloat162*)(g_ahi + i + 2) = __halves2bfloat162(h2,h3);
    *(__nv_bfloat162*)(g_alo + i)     = __halves2bfloat162(l0,l1);
    *(__nv_bfloat162*)(g_alo + i + 2) = __halves2bfloat162(l2,l3);
}

// ---------------- Input projection GEMM: pre-split bf16, cp.async, wmma ------
// g_gx[m][n] = sum_k A[m][k]*W[n][k] + bias[n], via ah*wh + ah*wl + al*wh.
// 128m x 128n tile, k-step 32, double-buffered cp.async, 8 warps (32m x 64n).
template<int K>
__global__ void __launch_bounds__(256, 2) gemm_bf16(const float* __restrict__ bias) {
    extern __shared__ __align__(16) __nv_bfloat16 ts[];   // [2][4][128][GLDA]
    int bm = blockIdx.y*128, bn = blockIdx.x*128;
    int tid = threadIdx.x, lane = tid & 31, wid = tid >> 5;
    int wm = wid >> 1, wn = wid & 1;

    unsigned sb = (unsigned)__cvta_generic_to_shared(ts);

    auto issue_stage = [&](int k0, int buf) {
        #pragma unroll
        for (int c = 0; c < 8; c++) {
            int chunk = tid + c*256;            // 2048 chunks of 16B
            int op = chunk >> 9;
            int r = (chunk >> 2) & 127;
            int seg = chunk & 3;
            const __nv_bfloat16* gp;
            if (op == 0)      gp = g_ahi + (size_t)(bm + r)*K + k0 + seg*8;
            else if (op == 1) gp = g_alo + (size_t)(bm + r)*K + k0 + seg*8;
            else if (op == 2) gp = g_whi + (size_t)(bn + r)*K + k0 + seg*8;
            else              gp = g_wlo + (size_t)(bn + r)*K + k0 + seg*8;
            unsigned dst = sb + (((buf*4 + op)*128 + r)*GLDA + seg*8)*2;
            asm volatile("cp.async.cg.shared.global [%0], [%1], 16;"
                         :: "r"(dst), "l"(gp));
        }
        asm volatile("cp.async.commit_group;");
    };
    auto plane = [&](int buf, int op) -> const __nv_bfloat16* {
        return ts + (size_t)((buf*4 + op)*128)*GLDA;
    };

    wmma::fragment<wmma::accumulator,16,16,16,float> acc[2][4];
    #pragma unroll
    for (int i = 0; i < 2; i++)
        #pragma unroll
        for (int j = 0; j < 4; j++) wmma::fill_fragment(acc[i][j], 0.0f);

    issue_stage(0, 0);
    int buf = 0;
    constexpr int S = K/32;
    for (int s = 0; s < S; s++) {
        if (s + 1 < S) {
            issue_stage((s+1)*32, buf ^ 1);
            asm volatile("cp.async.wait_group 1;");
        } else {
            asm volatile("cp.async.wait_group 0;");
        }
        __syncthreads();
        #pragma unroll
        for (int kk = 0; kk < 32; kk += 16) {
            wmma::fragment<wmma::matrix_a,16,16,16,__nv_bfloat16,wmma::row_major> fa_h[2], fa_l[2];
            #pragma unroll
            for (int i = 0; i < 2; i++) {
                wmma::load_matrix_sync(fa_h[i], plane(buf,0) + (wm*32 + i*16)*GLDA + kk, GLDA);
                wmma::load_matrix_sync(fa_l[i], plane(buf,1) + (wm*32 + i*16)*GLDA + kk, GLDA);
            }
            #pragma unroll
            for (int j = 0; j < 4; j++) {
                wmma::fragment<wmma::matrix_b,16,16,16,__nv_bfloat16,wmma::col_major> fb_h, fb_l;
                wmma::load_matrix_sync(fb_h, plane(buf,2) + (wn*64 + j*16)*GLDA + kk, GLDA);
                wmma::load_matrix_sync(fb_l, plane(buf,3) + (wn*64 + j*16)*GLDA + kk, GLDA);
                #pragma unroll
                for (int i = 0; i < 2; i++) {
                    wmma::mma_sync(acc[i][j], fa_h[i], fb_h, acc[i][j]);
                    wmma::mma_sync(acc[i][j], fa_h[i], fb_l, acc[i][j]);
                    wmma::mma_sync(acc[i][j], fa_l[i], fb_h, acc[i][j]);
                }
            }
        }
        __syncthreads();        // all reads of buf done before it is refilled
        buf ^= 1;
    }

    // epilogue: reuse ts as fp32 scratch
    float* scratch = reinterpret_cast<float*>(ts) + wid*320;   // 16x20 per warp
    #pragma unroll
    for (int i = 0; i < 2; i++)
        #pragma unroll
        for (int j = 0; j < 4; j++) {
            wmma::store_matrix_sync(scratch, acc[i][j], 20, wmma::mem_row_major);
            __syncwarp();
            int r = lane >> 1, cb = (lane & 1)*8;
            int row = bm + wm*32 + i*16 + r;
            int col = bn + wn*64 + j*16 + cb;
            float4 v0 = *(float4*)&scratch[r*20 + cb];
            float4 v1 = *(float4*)&scratch[r*20 + cb + 4];
            const float* bp = bias + col;
            float* gp = g_gx + (size_t)row*G3 + col;
            *(float4*)gp = make_float4(v0.x + bp[0], v0.y + bp[1], v0.z + bp[2], v0.w + bp[3]);
            *(float4*)(gp + 4) = make_float4(v1.x + bp[4], v1.y + bp[5], v1.z + bp[6], v1.w + bp[7]);
            __syncwarp();
        }
}

// ---------------- Persistent GRU layer: tensor-core recurrence (R9) ----------
// Change vs R9: modes 0/1 store y as pre-split bf16 hi/lo (g_ahi/g_alo, stride
// HO) -- feeds the next layer's GEMM directly; mode 2 stores fp32 masked out.
__global__ void __launch_bounds__(256) gru4(const float* __restrict__ whh,
                                            const float* __restrict__ bhh,
                                            float* __restrict__ dout,
                                            const int* __restrict__ seq_lens,
                                            int dst_mode) {
    extern __shared__ float sm[];
    float* h_sm  = sm;                       // BPG * HP   = 4128 floats
    float* red   = h_sm + BPG*HP;            // 24 * RMT   = 3840 floats
    float* bh_sm = red + 24*RMT;             // GROWS

    int tid = threadIdx.x, lane = tid & 31, warp = tid >> 5;
    int grp = blockIdx.x >> 5;
    int cig = blockIdx.x & 31;
    int jbase = cig * JPC;

    unsigned int base;
    asm volatile("ld.relaxed.gpu.u32 %0, [%1];" : "=r"(base)
                 : "l"(&g_gen2[grp]) : "memory");

    // preload W fragments into registers (split-bf16 hi/lo)
    unsigned awhi[3][4][4], awlo[3][4][4];
    {
        int r = lane >> 2, c = (lane & 3)*2;
        #pragma unroll
        for (int m = 0; m < 3; m++) {
            size_t row0 = (size_t)(m*HO + jbase + r)*HO;
            size_t row1 = row0 + 8*(size_t)HO;
            #pragma unroll
            for (int kt4 = 0; kt4 < 4; kt4++) {
                int kb = (warp*4 + kt4)*16 + c;
                float2 w00 = *(const float2*)(whh + row0 + kb);
                float2 w10 = *(const float2*)(whh + row1 + kb);
                float2 w01 = *(const float2*)(whh + row0 + kb + 8);
                float2 w11 = *(const float2*)(whh + row1 + kb + 8);
                split2(w00.x, w00.y, awhi[m][kt4][0], awlo[m][kt4][0]);
                split2(w10.x, w10.y, awhi[m][kt4][1], awlo[m][kt4][1]);
                split2(w01.x, w01.y, awhi[m][kt4][2], awlo[m][kt4][2]);
                split2(w11.x, w11.y, awhi[m][kt4][3], awlo[m][kt4][3]);
            }
        }
    }
    if (tid < GROWS) bh_sm[tid] = bhh[(tid >> 4)*HO + jbase + (tid & 15)];
    for (int i = tid; i < BPG*HO; i += 256)
        h_sm[(i >> 9)*HP + (i & (HO-1))] = 0.0f;

    const int gjj = tid & 15, gb = tid >> 4;
    const int b_glob = grp*BPG + gb;
    int slen = TT;
    if (dst_mode == 2 && tid < 128) slen = seq_lens[b_glob];

    float gxr = 0.f, gxz = 0.f, gxn = 0.f;
    if (tid < 128) {
        size_t bse = (size_t)b_glob*TT*G3 + jbase + gjj;
        gxr = g_gx[bse];
        gxz = g_gx[bse + HO];
        gxn = g_gx[bse + 2*HO];
    }
    __syncthreads();

    const int bq = lane >> 2;
    const int kc2 = (lane & 3)*2;

    for (int t = 0; t < TT; t++) {
        // tensor-core GEMV
        float d[3][4];
        #pragma unroll
        for (int m = 0; m < 3; m++)
            #pragma unroll
            for (int e = 0; e < 4; e++) d[m][e] = 0.0f;

        #pragma unroll
        for (int kt4 = 0; kt4 < 4; kt4++) {
            int kb = (warp*4 + kt4)*16 + kc2;
            const float* hp = h_sm + bq*HP + kb;
            float2 v0 = *(const float2*)(hp);
            float2 v1 = *(const float2*)(hp + 8);
            unsigned bh0, bl0, bh1, bl1;
            split2(v0.x, v0.y, bh0, bl0);
            split2(v1.x, v1.y, bh1, bl1);
            #pragma unroll
            for (int m = 0; m < 3; m++) {
                mma_bf16(d[m], awhi[m][kt4], bh0, bh1);
                mma_bf16(d[m], awhi[m][kt4], bl0, bl1);
                mma_bf16(d[m], awlo[m][kt4], bh0, bh1);
            }
        }
        #pragma unroll
        for (int m = 0; m < 3; m++) {
            float* rp = red + (warp*3 + m)*RMT + (lane>>2)*RROW + (lane&3)*2;
            *(float2*)rp            = make_float2(d[m][0], d[m][1]);
            *(float2*)(rp + 8*RROW) = make_float2(d[m][2], d[m][3]);
        }
        __syncthreads();

        // fused reduce + gate math
        float hn2 = 0.f;
        if (tid < 128) {
            float gh[3];
            #pragma unroll
            for (int g = 0; g < 3; g++) {
                const float* rp = red + g*RMT + gjj*RROW + gb;
                float s = 0.0f;
                #pragma unroll
                for (int w = 0; w < 8; w++)
                    s += rp[w*3*RMT];
                gh[g] = s + bh_sm[g*16 + gjj];
            }
            float r  = sigf(gxr + gh[0]);
            float zg = sigf(gxz + gh[1]);
            float n  = tanhfast(gxn + r*gh[2]);
            float hp = h_sm[gb*HP + jbase + gjj];
            hn2 = (1.0f - zg)*n + zg*hp;
            if (t < TT - 1)
                g_h2[grp][(t + 1) & 1][gb*HO + jbase + gjj] = hn2;
        }
        __syncthreads();

        if (t < TT - 1) {
            const unsigned tgt = base + (unsigned)(t + 1);
            if (tid == 0) {
                __threadfence();
                if (atomicAdd(&g_cnt2[grp], 1u) == CPG - 1u) {
                    g_cnt2[grp] = 0u;
                    __threadfence();
                    asm volatile("st.relaxed.gpu.u32 [%0], %1;"
                                 :: "l"(&g_gen2[grp]), "r"(tgt) : "memory");
                }
            }
            // overlapped with convergence: y store + gx(t+1) prefetch
            if (tid < 128) {
                size_t idx = ((size_t)b_glob*TT + t)*HO + jbase + gjj;
                if (dst_mode == 2) {
                    dout[idx] = (t < slen) ? hn2 : 0.0f;
                } else {
                    __nv_bfloat16 hi, lo;
                    split1(hn2, hi, lo);
                    g_ahi[idx] = hi;
                    g_alo[idx] = lo;
                }
                size_t bse = ((size_t)b_glob*TT + (t + 1))*G3 + jbase + gjj;
                gxr = g_gx[bse];
                gxz = g_gx[bse + HO];
                gxn = g_gx[bse + 2*HO];
            }
            unsigned v;
            do {
                asm volatile("ld.acquire.gpu.u32 %0, [%1];" : "=r"(v)
                             : "l"(&g_gen2[grp]) : "memory");
            } while ((int)(v - tgt) < 0);
            const float* hb = g_h2[grp][(t + 1) & 1];
            for (int i = tid*4; i < BPG*HO; i += 1024) {
                float4 hv = *(const float4*)(hb + i);
                *(float4*)(h_sm + (i >> 9)*HP + (i & (HO-1))) = hv;
            }
            __syncthreads();
        } else {
            if (tid < 128) {
                size_t idx = ((size_t)b_glob*TT + t)*HO + jbase + gjj;
                if (dst_mode == 2) {
                    dout[idx] = (t < slen) ? hn2 : 0.0f;
                } else {
                    __nv_bfloat16 hi, lo;
                    split1(hn2, hi, lo);
                    g_ahi[idx] = hi;
                    g_alo[idx] = lo;
                }
            }
        }
    }
}

// ---------------- launch ----------------------------------------------------
#define GRU_SMEM ((BPG*HP + 24*RMT + GROWS) * 4)
#define GEMM_SMEM (2*4*128*GLDA*2)

extern "C" void kernel_launch(void* const* d_in, const int* in_sizes, int n_in,
                              void* d_out, int out_size) {
    const float* z     = (const float*)d_in[0];
    const int*   seq   = (const int*)  d_in[1];
    const float* chord = (const float*)d_in[2];
    const float* fc_w  = (const float*)d_in[3];
    const float* fc_b  = (const float*)d_in[4];
    const float* w_ih0 = (const float*)d_in[5];
    const float* w_hh0 = (const float*)d_in[6];
    const float* b_ih0 = (const float*)d_in[7];
    const float* b_hh0 = (const float*)d_in[8];
    const float* w_ih1 = (const float*)d_in[9];
    const float* w_hh1 = (const float*)d_in[10];
    const float* b_ih1 = (const float*)d_in[11];
    const float* b_hh1 = (const float*)d_in[12];
    const float* w_ih2 = (const float*)d_in[13];
    const float* w_hh2 = (const float*)d_in[14];
    const float* b_ih2 = (const float*)d_in[15];
    const float* b_hh2 = (const float*)d_in[16];
    float* out = (float*)d_out;

    cudaFuncSetAttribute(gru4, cudaFuncAttributeMaxDynamicSharedMemorySize, GRU_SMEM);
    cudaFuncSetAttribute(gemm_bf16<HID>, cudaFuncAttributeMaxDynamicSharedMemorySize, GEMM_SMEM);
    cudaFuncSetAttribute(gemm_bf16<HO>,  cudaFuncAttributeMaxDynamicSharedMemorySize, GEMM_SMEM);

    dim3 ggrid(G3/128, MTOT/128);   // (12, 128)

    fc_kernel<<<BB, LAT>>>(z, fc_w, fc_b);
    split_a0<<<(int)(((size_t)MTOT*HID)/1024), 256>>>(chord);

    split_w<<<(G3*HID)/1024, 256>>>(w_ih0, G3*HID);
    gemm_bf16<HID><<<ggrid, 256, GEMM_SMEM>>>(b_ih0);
    gru4<<<NG*CPG, 256, GRU_SMEM>>>(w_hh0, b_hh0, nullptr, seq, 0);

    split_w<<<(G3*HO)/1024, 256>>>(w_ih1, G3*HO);
    gemm_bf16<HO><<<ggrid, 256, GEMM_SMEM>>>(b_ih1);
    gru4<<<NG*CPG, 256, GRU_SMEM>>>(w_hh1, b_hh1, nullptr, seq, 1);

    split_w<<<(G3*HO)/1024, 256>>>(w_ih2, G3*HO);
    gemm_bf16<HO><<<ggrid, 256, GEMM_SMEM>>>(b_ih2);
    gru4<<<NG*CPG, 256, GRU_SMEM>>>(w_hh2, b_hh2, out, seq, 2);
}

// round 12
// speedup vs baseline: 2.5645x; 1.3715x over previous
#include <cuda_runtime.h>
#include <cuda_bf16.h>
#include <mma.h>
#include <math.h>

using namespace nvcuda;

#define BB   32
#define TT   512
#define LAT  256
#define HID  1024
#define HO   512
#define G3   1536
#define MTOT (BB*TT)

// GRU partitioning: 4 independent groups x 8 batches, 32 CTAs per group.
#define NG   4
#define CPG  32
#define BPG  8
#define JPC  16
#define GROWS 48
#define RROW 10
#define RMT  160

#define GLDA 40          // bf16 elems per smem row in gemm (32 data + 8 pad = 80B)

// ---------------- scratch (device globals; no allocations allowed) ----------
__device__ float g_fc[BB*HID];
__device__ float g_gx[(size_t)MTOT*G3];
__device__ __nv_bfloat16 g_ahi[(size_t)MTOT*HID];   // A operand hi
__device__ __nv_bfloat16 g_alo[(size_t)MTOT*HID];   // A operand lo
__device__ __nv_bfloat16 g_whi[(size_t)G3*HID];     // W operand hi (re-split per layer)
__device__ __nv_bfloat16 g_wlo[(size_t)G3*HID];
__device__ float g_h2[NG][2][BPG*HO];
__device__ unsigned int g_flag[NG][CPG][32];        // per-CTA step flag, 128B padded

// fast gates (MUFU): rel err ~1e-6, budget 1e-3
__device__ __forceinline__ float sigf(float x) {
    return __fdividef(1.0f, 1.0f + __expf(-x));
}
__device__ __forceinline__ float tanhfast(float x) {
    return 2.0f * __fdividef(1.0f, 1.0f + __expf(-2.0f * x)) - 1.0f;
}

__device__ __forceinline__ void split1(float x, __nv_bfloat16& hi, __nv_bfloat16& lo) {
    hi = __float2bfloat16(x);
    lo = __float2bfloat16(x - __bfloat162float(hi));
}
__device__ __forceinline__ void split2(float x, float y, unsigned& hi, unsigned& lo) {
    __nv_bfloat16 hx, lx, hy, ly;
    split1(x, hx, lx); split1(y, hy, ly);
    __nv_bfloat162 h2 = __halves2bfloat162(hx, hy);
    __nv_bfloat162 l2 = __halves2bfloat162(lx, ly);
    hi = *reinterpret_cast<unsigned*>(&h2);
    lo = *reinterpret_cast<unsigned*>(&l2);
}

// mma.m16n8k16 row.col f32 += bf16 * bf16
__device__ __forceinline__ void mma_bf16(float d[4], const unsigned a[4],
                                         unsigned b0, unsigned b1) {
    asm volatile(
        "mma.sync.aligned.m16n8k16.row.col.f32.bf16.bf16.f32 "
        "{%0,%1,%2,%3}, {%4,%5,%6,%7}, {%8,%9}, {%0,%1,%2,%3};"
        : "+f"(d[0]), "+f"(d[1]), "+f"(d[2]), "+f"(d[3])
        : "r"(a[0]), "r"(a[1]), "r"(a[2]), "r"(a[3]), "r"(b0), "r"(b1));
}

// ---------------- FC + ReLU --------------------------------------------------
__global__ void fc_kernel(const float* __restrict__ z,
                          const float* __restrict__ fc_w,
                          const float* __restrict__ fc_b) {
    __shared__ float zs[LAT];
    int b = blockIdx.x;
    zs[threadIdx.x] = z[b*LAT + threadIdx.x];
    __syncthreads();
    for (int h = threadIdx.x; h < HID; h += blockDim.x) {
        const float4* w = (const float4*)(fc_w + (size_t)h*LAT);
        float s = fc_b[h];
        #pragma unroll 8
        for (int k = 0; k < LAT/4; k++) {
            float4 wv = w[k];
            float4 zv = *(const float4*)(zs + 4*k);
            s += wv.x*zv.x + wv.y*zv.y + wv.z*zv.z + wv.w*zv.w;
        }
        g_fc[b*HID + h] = fmaxf(s, 0.0f);
    }
}

// ---------------- split prepasses -------------------------------------------
__global__ void split_w(const float* __restrict__ W, int n) {
    int i = (blockIdx.x*256 + threadIdx.x)*4;
    if (i >= n) return;
    float4 v = *(const float4*)(W + i);
    __nv_bfloat16 h0,l0,h1,l1,h2,l2,h3,l3;
    split1(v.x,h0,l0); split1(v.y,h1,l1); split1(v.z,h2,l2); split1(v.w,h3,l3);
    *(__nv_bfloat162*)(g_whi + i)     = __halves2bfloat162(h0,h1);
    *(__nv_bfloat162*)(g_whi + i + 2) = __halves2bfloat162(h2,h3);
    *(__nv_bfloat162*)(g_wlo + i)     = __halves2bfloat162(l0,l1);
    *(__nv_bfloat162*)(g_wlo + i + 2) = __halves2bfloat162(l2,l3);
}

__global__ void split_a0(const float* __restrict__ chord) {
    size_t i = ((size_t)blockIdx.x*256 + threadIdx.x)*4;
    int m = (int)(i >> 10);
    int k = (int)(i & (HID-1));
    int b = m >> 9;
    float4 f = *(const float4*)(g_fc + (size_t)b*HID + k);
    float4 c = *(const float4*)(chord + i);
    float a0 = f.x + 0.01f*c.x, a1 = f.y + 0.01f*c.y;
    float a2 = f.z + 0.01f*c.z, a3 = f.w + 0.01f*c.w;
    __nv_bfloat16 h0,l0,h1,l1,h2,l2,h3,l3;
    split1(a0,h0,l0); split1(a1,h1,l1); split1(a2,h2,l2); split1(a3,h3,l3);
    *(__nv_bfloat162*)(g_ahi + i)     = __halves2bfloat162(h0,h1);
    *(__nv_bfloat162*)(g_ahi + i + 2) = __halves2bfloat162(h2,h3);
    *(__nv_bfloat162*)(g_alo + i)     = __halves2bfloat162(l0,l1);
    *(__nv_bfloat162*)(g_alo + i + 2) = __halves2bfloat162(l2,l3);
}

// ---------------- Input projection GEMM: pre-split bf16, cp.async, wmma ------
template<int K>
__global__ void __launch_bounds__(256, 2) gemm_bf16(const float* __restrict__ bias) {
    extern __shared__ __align__(16) __nv_bfloat16 ts[];   // [2][4][128][GLDA]
    int bm = blockIdx.y*128, bn = blockIdx.x*128;
    int tid = threadIdx.x, lane = tid & 31, wid = tid >> 5;
    int wm = wid >> 1, wn = wid & 1;

    unsigned sb = (unsigned)__cvta_generic_to_shared(ts);

    auto issue_stage = [&](int k0, int buf) {
        #pragma unroll
        for (int c = 0; c < 8; c++) {
            int chunk = tid + c*256;
            int op = chunk >> 9;
            int r = (chunk >> 2) & 127;
            int seg = chunk & 3;
            const __nv_bfloat16* gp;
            if (op == 0)      gp = g_ahi + (size_t)(bm + r)*K + k0 + seg*8;
            else if (op == 1) gp = g_alo + (size_t)(bm + r)*K + k0 + seg*8;
            else if (op == 2) gp = g_whi + (size_t)(bn + r)*K + k0 + seg*8;
            else              gp = g_wlo + (size_t)(bn + r)*K + k0 + seg*8;
            unsigned dst = sb + (((buf*4 + op)*128 + r)*GLDA + seg*8)*2;
            asm volatile("cp.async.cg.shared.global [%0], [%1], 16;"
                         :: "r"(dst), "l"(gp));
        }
        asm volatile("cp.async.commit_group;");
    };
    auto plane = [&](int buf, int op) -> const __nv_bfloat16* {
        return ts + (size_t)((buf*4 + op)*128)*GLDA;
    };

    wmma::fragment<wmma::accumulator,16,16,16,float> acc[2][4];
    #pragma unroll
    for (int i = 0; i < 2; i++)
        #pragma unroll
        for (int j = 0; j < 4; j++) wmma::fill_fragment(acc[i][j], 0.0f);

    issue_stage(0, 0);
    int buf = 0;
    constexpr int S = K/32;
    for (int s = 0; s < S; s++) {
        if (s + 1 < S) {
            issue_stage((s+1)*32, buf ^ 1);
            asm volatile("cp.async.wait_group 1;");
        } else {
            asm volatile("cp.async.wait_group 0;");
        }
        __syncthreads();
        #pragma unroll
        for (int kk = 0; kk < 32; kk += 16) {
            wmma::fragment<wmma::matrix_a,16,16,16,__nv_bfloat16,wmma::row_major> fa_h[2], fa_l[2];
            #pragma unroll
            for (int i = 0; i < 2; i++) {
                wmma::load_matrix_sync(fa_h[i], plane(buf,0) + (wm*32 + i*16)*GLDA + kk, GLDA);
                wmma::load_matrix_sync(fa_l[i], plane(buf,1) + (wm*32 + i*16)*GLDA + kk, GLDA);
            }
            #pragma unroll
            for (int j = 0; j < 4; j++) {
                wmma::fragment<wmma::matrix_b,16,16,16,__nv_bfloat16,wmma::col_major> fb_h, fb_l;
                wmma::load_matrix_sync(fb_h, plane(buf,2) + (wn*64 + j*16)*GLDA + kk, GLDA);
                wmma::load_matrix_sync(fb_l, plane(buf,3) + (wn*64 + j*16)*GLDA + kk, GLDA);
                #pragma unroll
                for (int i = 0; i < 2; i++) {
                    wmma::mma_sync(acc[i][j], fa_h[i], fb_h, acc[i][j]);
                    wmma::mma_sync(acc[i][j], fa_h[i], fb_l, acc[i][j]);
                    wmma::mma_sync(acc[i][j], fa_l[i], fb_h, acc[i][j]);
                }
            }
        }
        __syncthreads();
        buf ^= 1;
    }

    float* scratch = reinterpret_cast<float*>(ts) + wid*320;
    #pragma unroll
    for (int i = 0; i < 2; i++)
        #pragma unroll
        for (int j = 0; j < 4; j++) {
            wmma::store_matrix_sync(scratch, acc[i][j], 20, wmma::mem_row_major);
            __syncwarp();
            int r = lane >> 1, cb = (lane & 1)*8;
            int row = bm + wm*32 + i*16 + r;
            int col = bn + wn*64 + j*16 + cb;
            float4 v0 = *(float4*)&scratch[r*20 + cb];
            float4 v1 = *(float4*)&scratch[r*20 + cb + 4];
            const float* bp = bias + col;
            float* gp = g_gx + (size_t)row*G3 + col;
            *(float4*)gp = make_float4(v0.x + bp[0], v0.y + bp[1], v0.z + bp[2], v0.w + bp[3]);
            *(float4*)(gp + 4) = make_float4(v1.x + bp[4], v1.y + bp[5], v1.z + bp[6], v1.w + bp[7]);
            __syncwarp();
        }
}

// ---------------- Persistent GRU: fine-grained producer flags ----------------
// Warp w consumes h[k] only for k in [64w, 64w+64) = outputs of CTAs 4w..4w+3.
// Each CTA: computes its 128 h values, STGs them, bar.sync, tid0 st.release
// bumps its flag. Consumer warps spin on just their 4 producers' flags (one
// lane each), then LDG the 2KB slice straight into mma B-frags. h_prev for the
// gate update lives in a register (thread (b,j) is its own producer).
// Safety: a CTA writes buf[t&1] at iter t+1 only after its syncthreads joined
// warps that observed ALL 32 flags >= t+1, which happens-after every CTA's
// iter-t reads of buf[t&1].
__global__ void __launch_bounds__(256) gru5(const float* __restrict__ whh,
                                            const float* __restrict__ bhh,
                                            float* __restrict__ dout,
                                            const int* __restrict__ seq_lens,
                                            int dst_mode) {
    __shared__ float red[24*RMT];
    __shared__ float bh_sm[GROWS];

    int tid = threadIdx.x, lane = tid & 31, warp = tid >> 5;
    int grp = blockIdx.x >> 5;
    int cig = blockIdx.x & 31;
    int jbase = cig * JPC;

    // monotonic flag base: all flags in the group are equal at launch entry
    unsigned int base;
    asm volatile("ld.relaxed.gpu.u32 %0, [%1];" : "=r"(base)
                 : "l"(&g_flag[grp][cig][0]) : "memory");

    // preload W fragments into registers (split-bf16 hi/lo)
    unsigned awhi[3][4][4], awlo[3][4][4];
    {
        int r = lane >> 2, c = (lane & 3)*2;
        #pragma unroll
        for (int m = 0; m < 3; m++) {
            size_t row0 = (size_t)(m*HO + jbase + r)*HO;
            size_t row1 = row0 + 8*(size_t)HO;
            #pragma unroll
            for (int kt4 = 0; kt4 < 4; kt4++) {
                int kb = (warp*4 + kt4)*16 + c;
                float2 w00 = *(const float2*)(whh + row0 + kb);
                float2 w10 = *(const float2*)(whh + row1 + kb);
                float2 w01 = *(const float2*)(whh + row0 + kb + 8);
                float2 w11 = *(const float2*)(whh + row1 + kb + 8);
                split2(w00.x, w00.y, awhi[m][kt4][0], awlo[m][kt4][0]);
                split2(w10.x, w10.y, awhi[m][kt4][1], awlo[m][kt4][1]);
                split2(w01.x, w01.y, awhi[m][kt4][2], awlo[m][kt4][2]);
                split2(w11.x, w11.y, awhi[m][kt4][3], awlo[m][kt4][3]);
            }
        }
    }
    if (tid < GROWS) bh_sm[tid] = bhh[(tid >> 4)*HO + jbase + (tid & 15)];

    const int gjj = tid & 15, gb = tid >> 4;
    const int b_glob = grp*BPG + gb;
    int slen = TT;
    if (dst_mode == 2 && tid < 128) slen = seq_lens[b_glob];

    float gxr = 0.f, gxz = 0.f, gxn = 0.f;
    if (tid < 128) {
        size_t bse = (size_t)b_glob*TT*G3 + jbase + gjj;
        gxr = g_gx[bse];
        gxz = g_gx[bse + HO];
        gxn = g_gx[bse + 2*HO];
    }
    float h_prev = 0.0f;          // own h(t)[gb][jbase+gjj] (tid<128)
    __syncthreads();

    const int bq = lane >> 2;             // B-frag batch index
    const int kc2 = (lane & 3)*2;         // B-frag k offset
    // this warp's producer flag (4 lanes poll 4 producers)
    const unsigned* my_flag = &g_flag[grp][warp*4 + (lane & 3)][0];

    for (int t = 0; t < TT; t++) {
        // ---- wait for this warp's 4 producers, then LDG h slice ----
        float2 hv0[4], hv1[4];
        if (t == 0) {
            #pragma unroll
            for (int kt4 = 0; kt4 < 4; kt4++) {
                hv0[kt4] = make_float2(0.f, 0.f);
                hv1[kt4] = make_float2(0.f, 0.f);
            }
        } else {
            const unsigned tgt = base + (unsigned)t;
            unsigned v;
            do {
                asm volatile("ld.acquire.gpu.u32 %0, [%1];" : "=r"(v)
                             : "l"(my_flag) : "memory");
            } while ((int)(v - tgt) < 0);
            __syncwarp();
            const float* hb = g_h2[grp][t & 1] + bq*HO;
            #pragma unroll
            for (int kt4 = 0; kt4 < 4; kt4++) {
                int kb = (warp*4 + kt4)*16 + kc2;
                hv0[kt4] = *(const float2*)(hb + kb);
                hv1[kt4] = *(const float2*)(hb + kb + 8);
            }
        }

        // ---- tensor-core GEMV ----
        float d[3][4];
        #pragma unroll
        for (int m = 0; m < 3; m++)
            #pragma unroll
            for (int e = 0; e < 4; e++) d[m][e] = 0.0f;

        #pragma unroll
        for (int kt4 = 0; kt4 < 4; kt4++) {
            unsigned bh0, bl0, bh1, bl1;
            split2(hv0[kt4].x, hv0[kt4].y, bh0, bl0);
            split2(hv1[kt4].x, hv1[kt4].y, bh1, bl1);
            #pragma unroll
            for (int m = 0; m < 3; m++) {
                mma_bf16(d[m], awhi[m][kt4], bh0, bh1);
                mma_bf16(d[m], awhi[m][kt4], bl0, bl1);
                mma_bf16(d[m], awlo[m][kt4], bh0, bh1);
            }
        }
        #pragma unroll
        for (int m = 0; m < 3; m++) {
            float* rp = red + (warp*3 + m)*RMT + (lane>>2)*RROW + (lane&3)*2;
            *(float2*)rp            = make_float2(d[m][0], d[m][1]);
            *(float2*)(rp + 8*RROW) = make_float2(d[m][2], d[m][3]);
        }
        __syncthreads();

        // ---- fused reduce + gate math (tid<128) ----
        float hn2 = 0.f;
        if (tid < 128) {
            float gh[3];
            #pragma unroll
            for (int g = 0; g < 3; g++) {
                const float* rp = red + g*RMT + gjj*RROW + gb;
                float s = 0.0f;
                #pragma unroll
                for (int w = 0; w < 8; w++)
                    s += rp[w*3*RMT];
                gh[g] = s + bh_sm[g*16 + gjj];
            }
            float r  = sigf(gxr + gh[0]);
            float zg = sigf(gxz + gh[1]);
            float n  = tanhfast(gxn + r*gh[2]);
            hn2 = (1.0f - zg)*n + zg*h_prev;
            h_prev = hn2;
            if (t < TT - 1)
                g_h2[grp][(t + 1) & 1][gb*HO + jbase + gjj] = hn2;
        }
        __syncthreads();            // h stores + red reads complete CTA-wide

        if (t < TT - 1) {
            // publish: bump own flag (release orders the h stores via bar.sync)
            if (tid == 0) {
                asm volatile("st.release.gpu.u32 [%0], %1;"
                             :: "l"(&g_flag[grp][cig][0]),
                                "r"(base + (unsigned)(t + 1)) : "memory");
            }
            // overlapped with consumers noticing: y store + gx(t+1) prefetch
            if (tid < 128) {
                size_t idx = ((size_t)b_glob*TT + t)*HO + jbase + gjj;
                if (dst_mode == 2) {
                    dout[idx] = (t < slen) ? hn2 : 0.0f;
                } else {
                    __nv_bfloat16 hi, lo;
                    split1(hn2, hi, lo);
                    g_ahi[idx] = hi;
                    g_alo[idx] = lo;
                }
                size_t bse = ((size_t)b_glob*TT + (t + 1))*G3 + jbase + gjj;
                gxr = g_gx[bse];
                gxz = g_gx[bse + HO];
                gxn = g_gx[bse + 2*HO];
            }
        } else {
            if (tid < 128) {
                size_t idx = ((size_t)b_glob*TT + t)*HO + jbase + gjj;
                if (dst_mode == 2) {
                    dout[idx] = (t < slen) ? hn2 : 0.0f;
                } else {
                    __nv_bfloat16 hi, lo;
                    split1(hn2, hi, lo);
                    g_ahi[idx] = hi;
                    g_alo[idx] = lo;
                }
            }
        }
    }
}

// ---------------- launch ----------------------------------------------------
#define GEMM_SMEM (2*4*128*GLDA*2)

extern "C" void kernel_launch(void* const* d_in, const int* in_sizes, int n_in,
                              void* d_out, int out_size) {
    const float* z     = (const float*)d_in[0];
    const int*   seq   = (const int*)  d_in[1];
    const float* chord = (const float*)d_in[2];
    const float* fc_w  = (const float*)d_in[3];
    const float* fc_b  = (const float*)d_in[4];
    const float* w_ih0 = (const float*)d_in[5];
    const float* w_hh0 = (const float*)d_in[6];
    const float* b_ih0 = (const float*)d_in[7];
    const float* b_hh0 = (const float*)d_in[8];
    const float* w_ih1 = (const float*)d_in[9];
    const float* w_hh1 = (const float*)d_in[10];
    const float* b_ih1 = (const float*)d_in[11];
    const float* b_hh1 = (const float*)d_in[12];
    const float* w_ih2 = (const float*)d_in[13];
    const float* w_hh2 = (const float*)d_in[14];
    const float* b_ih2 = (const float*)d_in[15];
    const float* b_hh2 = (const float*)d_in[16];
    float* out = (float*)d_out;

    cudaFuncSetAttribute(gemm_bf16<HID>, cudaFuncAttributeMaxDynamicSharedMemorySize, GEMM_SMEM);
    cudaFuncSetAttribute(gemm_bf16<HO>,  cudaFuncAttributeMaxDynamicSharedMemorySize, GEMM_SMEM);

    dim3 ggrid(G3/128, MTOT/128);   // (12, 128)

    fc_kernel<<<BB, LAT>>>(z, fc_w, fc_b);
    split_a0<<<(int)(((size_t)MTOT*HID)/1024), 256>>>(chord);

    split_w<<<(G3*HID)/1024, 256>>>(w_ih0, G3*HID);
    gemm_bf16<HID><<<ggrid, 256, GEMM_SMEM>>>(b_ih0);
    gru5<<<NG*CPG, 256>>>(w_hh0, b_hh0, nullptr, seq, 0);

    split_w<<<(G3*HO)/1024, 256>>>(w_ih1, G3*HO);
    gemm_bf16<HO><<<ggrid, 256, GEMM_SMEM>>>(b_ih1);
    gru5<<<NG*CPG, 256>>>(w_hh1, b_hh1, nullptr, seq, 1);

    split_w<<<(G3*HO)/1024, 256>>>(w_ih2, G3*HO);
    gemm_bf16<HO><<<ggrid, 256, GEMM_SMEM>>>(b_ih2);
    gru5<<<NG*CPG, 256>>>(w_hh2, b_hh2, out, seq, 2);
}

// round 13
// speedup vs baseline: 2.9171x; 1.1375x over previous
#include <cuda_runtime.h>
#include <cuda_bf16.h>
#include <mma.h>
#include <math.h>

using namespace nvcuda;

#define BB   32
#define TT   512
#define LAT  256
#define HID  1024
#define HO   512
#define G3   1536
#define MTOT (BB*TT)

// GRU partitioning: 4 independent groups x 8 batches, 32 CTAs per group.
#define NG   4
#define CPG  32
#define BPG  8
#define JPC  16
#define GROWS 48
#define RROW 10
#define RMT  160

#define GLDA 40          // bf16 elems per smem row in gemm (32 data + 8 pad = 80B)

// ---------------- scratch (device globals; no allocations allowed) ----------
__device__ float g_fc[BB*HID];
__device__ float g_gx[(size_t)MTOT*G3];
__device__ __nv_bfloat16 g_ahi[(size_t)MTOT*HID];   // A operand hi
__device__ __nv_bfloat16 g_alo[(size_t)MTOT*HID];   // A operand lo
__device__ __nv_bfloat16 g_whi[(size_t)G3*HID];     // W operand hi (re-split per layer)
__device__ __nv_bfloat16 g_wlo[(size_t)G3*HID];
// stamped hidden state: low 32 = packed bf16 (hi | lo<<16), high 32 = stamp
__device__ unsigned long long g_hs[NG][2][BPG*HO];
__device__ unsigned int g_epoch[NG][CPG][8];        // per-CTA stamp base, padded

// fast gates (MUFU): rel err ~1e-6, budget 1e-3
__device__ __forceinline__ float sigf(float x) {
    return __fdividef(1.0f, 1.0f + __expf(-x));
}
__device__ __forceinline__ float tanhfast(float x) {
    return 2.0f * __fdividef(1.0f, 1.0f + __expf(-2.0f * x)) - 1.0f;
}

__device__ __forceinline__ void split1(float x, __nv_bfloat16& hi, __nv_bfloat16& lo) {
    hi = __float2bfloat16(x);
    lo = __float2bfloat16(x - __bfloat162float(hi));
}
__device__ __forceinline__ void split2(float x, float y, unsigned& hi, unsigned& lo) {
    __nv_bfloat16 hx, lx, hy, ly;
    split1(x, hx, lx); split1(y, hy, ly);
    __nv_bfloat162 h2 = __halves2bfloat162(hx, hy);
    __nv_bfloat162 l2 = __halves2bfloat162(lx, ly);
    hi = *reinterpret_cast<unsigned*>(&h2);
    lo = *reinterpret_cast<unsigned*>(&l2);
}
__device__ __forceinline__ unsigned prmtb(unsigned a, unsigned b, unsigned sel) {
    unsigned d;
    asm("prmt.b32 %0, %1, %2, %3;" : "=r"(d) : "r"(a), "r"(b), "r"(sel));
    return d;
}

// mma.m16n8k16 row.col f32 += bf16 * bf16
__device__ __forceinline__ void mma_bf16(float d[4], const unsigned a[4],
                                         unsigned b0, unsigned b1) {
    asm volatile(
        "mma.sync.aligned.m16n8k16.row.col.f32.bf16.bf16.f32 "
        "{%0,%1,%2,%3}, {%4,%5,%6,%7}, {%8,%9}, {%0,%1,%2,%3};"
        : "+f"(d[0]), "+f"(d[1]), "+f"(d[2]), "+f"(d[3])
        : "r"(a[0]), "r"(a[1]), "r"(a[2]), "r"(a[3]), "r"(b0), "r"(b1));
}

// ---------------- FC + ReLU --------------------------------------------------
__global__ void fc_kernel(const float* __restrict__ z,
                          const float* __restrict__ fc_w,
                          const float* __restrict__ fc_b) {
    __shared__ float zs[LAT];
    int b = blockIdx.x;
    zs[threadIdx.x] = z[b*LAT + threadIdx.x];
    __syncthreads();
    for (int h = threadIdx.x; h < HID; h += blockDim.x) {
        const float4* w = (const float4*)(fc_w + (size_t)h*LAT);
        float s = fc_b[h];
        #pragma unroll 8
        for (int k = 0; k < LAT/4; k++) {
            float4 wv = w[k];
            float4 zv = *(const float4*)(zs + 4*k);
            s += wv.x*zv.x + wv.y*zv.y + wv.z*zv.z + wv.w*zv.w;
        }
        g_fc[b*HID + h] = fmaxf(s, 0.0f);
    }
}

// ---------------- split prepasses -------------------------------------------
__global__ void split_w(const float* __restrict__ W, int n) {
    int i = (blockIdx.x*256 + threadIdx.x)*4;
    if (i >= n) return;
    float4 v = *(const float4*)(W + i);
    __nv_bfloat16 h0,l0,h1,l1,h2,l2,h3,l3;
    split1(v.x,h0,l0); split1(v.y,h1,l1); split1(v.z,h2,l2); split1(v.w,h3,l3);
    *(__nv_bfloat162*)(g_whi + i)     = __halves2bfloat162(h0,h1);
    *(__nv_bfloat162*)(g_whi + i + 2) = __halves2bfloat162(h2,h3);
    *(__nv_bfloat162*)(g_wlo + i)     = __halves2bfloat162(l0,l1);
    *(__nv_bfloat162*)(g_wlo + i + 2) = __halves2bfloat162(l2,l3);
}

__global__ void split_a0(const float* __restrict__ chord) {
    size_t i = ((size_t)blockIdx.x*256 + threadIdx.x)*4;
    int m = (int)(i >> 10);
    int k = (int)(i & (HID-1));
    int b = m >> 9;
    float4 f = *(const float4*)(g_fc + (size_t)b*HID + k);
    float4 c = *(const float4*)(chord + i);
    float a0 = f.x + 0.01f*c.x, a1 = f.y + 0.01f*c.y;
    float a2 = f.z + 0.01f*c.z, a3 = f.w + 0.01f*c.w;
    __nv_bfloat16 h0,l0,h1,l1,h2,l2,h3,l3;
    split1(a0,h0,l0); split1(a1,h1,l1); split1(a2,h2,l2); split1(a3,h3,l3);
    *(__nv_bfloat162*)(g_ahi + i)     = __halves2bfloat162(h0,h1);
    *(__nv_bfloat162*)(g_ahi + i + 2) = __halves2bfloat162(h2,h3);
    *(__nv_bfloat162*)(g_alo + i)     = __halves2bfloat162(l0,l1);
    *(__nv_bfloat162*)(g_alo + i + 2) = __halves2bfloat162(l2,l3);
}

// ---------------- Input projection GEMM: 128x256 block, 64x64 warp tiles -----
// cp.async pre-split bf16 planes; 8 warps in 2x4; 4x4 16x16 frags per warp.
template<int K>
__global__ void __launch_bounds__(256, 1) gemm_bf16(const float* __restrict__ bias) {
    extern __shared__ __align__(16) __nv_bfloat16 ts[];   // [2][768][GLDA]
    int bm = blockIdx.y*128, bn = blockIdx.x*256;
    int tid = threadIdx.x, lane = tid & 31, wid = tid >> 5;
    int wm = wid >> 2, wn = wid & 3;      // warp tile origin (wm*64, wn*64)

    unsigned sb = (unsigned)__cvta_generic_to_shared(ts);

    // rowid 0-127 Ahi, 128-255 Alo, 256-511 Bhi, 512-767 Blo; 4 16B chunks/row
    auto issue_stage = [&](int k0, int buf) {
        #pragma unroll
        for (int c = 0; c < 12; c++) {
            int chunk = tid + c*256;
            int seg = chunk & 3;
            int rowid = chunk >> 2;
            const __nv_bfloat16* gp;
            if (rowid < 128)      gp = g_ahi + (size_t)(bm + rowid)*K       + k0 + seg*8;
            else if (rowid < 256) gp = g_alo + (size_t)(bm + rowid - 128)*K + k0 + seg*8;
            else if (rowid < 512) gp = g_whi + (size_t)(bn + rowid - 256)*K + k0 + seg*8;
            else                  gp = g_wlo + (size_t)(bn + rowid - 512)*K + k0 + seg*8;
            unsigned dst = sb + ((buf*768 + rowid)*GLDA + seg*8)*2;
            asm volatile("cp.async.cg.shared.global [%0], [%1], 16;"
                         :: "r"(dst), "l"(gp));
        }
        asm volatile("cp.async.commit_group;");
    };
    auto plane = [&](int buf, int op) -> const __nv_bfloat16* {
        // op: 0 Ahi, 1 Alo, 2 Bhi, 3 Blo (B planes are 256 rows)
        int rowbase = (op == 0) ? 0 : (op == 1) ? 128 : (op == 2) ? 256 : 512;
        return ts + (size_t)(buf*768 + rowbase)*GLDA;
    };

    wmma::fragment<wmma::accumulator,16,16,16,float> acc[4][4];
    #pragma unroll
    for (int i = 0; i < 4; i++)
        #pragma unroll
        for (int j = 0; j < 4; j++) wmma::fill_fragment(acc[i][j], 0.0f);

    issue_stage(0, 0);
    int buf = 0;
    constexpr int S = K/32;
    for (int s = 0; s < S; s++) {
        if (s + 1 < S) {
            issue_stage((s+1)*32, buf ^ 1);
            asm volatile("cp.async.wait_group 1;");
        } else {
            asm volatile("cp.async.wait_group 0;");
        }
        __syncthreads();
        #pragma unroll
        for (int kk = 0; kk < 32; kk += 16) {
            wmma::fragment<wmma::matrix_a,16,16,16,__nv_bfloat16,wmma::row_major> fa_h[4], fa_l[4];
            #pragma unroll
            for (int i = 0; i < 4; i++) {
                wmma::load_matrix_sync(fa_h[i], plane(buf,0) + (wm*64 + i*16)*GLDA + kk, GLDA);
                wmma::load_matrix_sync(fa_l[i], plane(buf,1) + (wm*64 + i*16)*GLDA + kk, GLDA);
            }
            #pragma unroll
            for (int j = 0; j < 4; j++) {
                wmma::fragment<wmma::matrix_b,16,16,16,__nv_bfloat16,wmma::col_major> fb_h, fb_l;
                wmma::load_matrix_sync(fb_h, plane(buf,2) + (wn*64 + j*16)*GLDA + kk, GLDA);
                wmma::load_matrix_sync(fb_l, plane(buf,3) + (wn*64 + j*16)*GLDA + kk, GLDA);
                #pragma unroll
                for (int i = 0; i < 4; i++) {
                    wmma::mma_sync(acc[i][j], fa_h[i], fb_h, acc[i][j]);
                    wmma::mma_sync(acc[i][j], fa_h[i], fb_l, acc[i][j]);
                    wmma::mma_sync(acc[i][j], fa_l[i], fb_h, acc[i][j]);
                }
            }
        }
        __syncthreads();
        buf ^= 1;
    }

    float* scratch = reinterpret_cast<float*>(ts) + wid*320;   // 16x20 per warp
    #pragma unroll
    for (int i = 0; i < 4; i++)
        #pragma unroll
        for (int j = 0; j < 4; j++) {
            wmma::store_matrix_sync(scratch, acc[i][j], 20, wmma::mem_row_major);
            __syncwarp();
            int r = lane >> 1, cb = (lane & 1)*8;
            int row = bm + wm*64 + i*16 + r;
            int col = bn + wn*64 + j*16 + cb;
            float4 v0 = *(float4*)&scratch[r*20 + cb];
            float4 v1 = *(float4*)&scratch[r*20 + cb + 4];
            const float* bp = bias + col;
            float* gp = g_gx + (size_t)row*G3 + col;
            *(float4*)gp = make_float4(v0.x + bp[0], v0.y + bp[1], v0.z + bp[2], v0.w + bp[3]);
            *(float4*)(gp + 4) = make_float4(v1.x + bp[4], v1.y + bp[5], v1.z + bp[6], v1.w + bp[7]);
            __syncwarp();
        }
}

// ---------------- Persistent GRU: stamped-data exchange ----------------------
// h published as one 8B word {packed bf16 hi|lo<<16, stamp = base+t}. 8B-aligned
// stores/loads are HW-atomic, so a stamp match certifies the h value in the same
// word -> consumers poll the data directly (ONE L2 trip; no flags, no 2nd LDG).
// Buffer WAR safety: CTA A writes buf[(t+1)&1] at gate(t) only after A's warps
// consumed stamps==t for ALL 32 producers; producer B stamped h(t) only after
// B's GEMV(t-1) reads of buf[(t-1)&1] completed (values already in regs). So
// A's write happens-after every read of that buffer parity. red[] is double-
// buffered -> ONE __syncthreads per step (ordering across iters via barrier).
__global__ void __launch_bounds__(256) gru6(const float* __restrict__ whh,
                                            const float* __restrict__ bhh,
                                            float* __restrict__ dout,
                                            const int* __restrict__ seq_lens,
                                            int dst_mode) {
    __shared__ float red[2][24*RMT];
    __shared__ float bh_sm[GROWS];

    int tid = threadIdx.x, lane = tid & 31, warp = tid >> 5;
    int grp = blockIdx.x >> 5;
    int cig = blockIdx.x & 31;
    int jbase = cig * JPC;

    // stamp base: all CTAs of a group increment their own slot by TT per launch
    unsigned base = g_epoch[grp][cig][0];

    // preload W fragments into registers (split-bf16 hi/lo)
    unsigned awhi[3][4][4], awlo[3][4][4];
    {
        int r = lane >> 2, c = (lane & 3)*2;
        #pragma unroll
        for (int m = 0; m < 3; m++) {
            size_t row0 = (size_t)(m*HO + jbase + r)*HO;
            size_t row1 = row0 + 8*(size_t)HO;
            #pragma unroll
            for (int kt4 = 0; kt4 < 4; kt4++) {
                int kb = (warp*4 + kt4)*16 + c;
                float2 w00 = *(const float2*)(whh + row0 + kb);
                float2 w10 = *(const float2*)(whh + row1 + kb);
                float2 w01 = *(const float2*)(whh + row0 + kb + 8);
                float2 w11 = *(const float2*)(whh + row1 + kb + 8);
                split2(w00.x, w00.y, awhi[m][kt4][0], awlo[m][kt4][0]);
                split2(w10.x, w10.y, awhi[m][kt4][1], awlo[m][kt4][1]);
                split2(w01.x, w01.y, awhi[m][kt4][2], awlo[m][kt4][2]);
                split2(w11.x, w11.y, awhi[m][kt4][3], awlo[m][kt4][3]);
            }
        }
    }
    if (tid < GROWS) bh_sm[tid] = bhh[(tid >> 4)*HO + jbase + (tid & 15)];

    const int gjj = tid & 15, gb = tid >> 4;
    const int b_glob = grp*BPG + gb;
    int slen = TT;
    if (dst_mode == 2 && tid < 128) slen = seq_lens[b_glob];

    float gxr = 0.f, gxz = 0.f, gxn = 0.f;
    if (tid < 128) {
        size_t bse = (size_t)b_glob*TT*G3 + jbase + gjj;
        gxr = g_gx[bse];
        gxz = g_gx[bse + HO];
        gxn = g_gx[bse + 2*HO];
    }
    float h_prev = 0.0f;
    __syncthreads();

    const int bq = lane >> 2;             // B-frag batch index
    const int kc2 = (lane & 3)*2;         // B-frag k offset

    for (int t = 0; t < TT; t++) {
        // ---- obtain h(t): poll stamped words (t>0) or zeros ----
        unsigned long long w[4][4];
        if (t == 0) {
            #pragma unroll
            for (int a = 0; a < 4; a++)
                #pragma unroll
                for (int e = 0; e < 4; e++) w[a][e] = 0ull;
        } else {
            const unsigned tgt = base + (unsigned)t;
            const unsigned long long* hb = g_hs[grp][t & 1] + bq*HO;
            bool ok;
            do {
                ok = true;
                #pragma unroll
                for (int kt4 = 0; kt4 < 4; kt4++) {
                    int kb = (warp*4 + kt4)*16 + kc2;
                    const unsigned long long* p = hb + kb;
                    asm volatile("ld.relaxed.gpu.global.u64 %0, [%1];" : "=l"(w[kt4][0]) : "l"(p));
                    asm volatile("ld.relaxed.gpu.global.u64 %0, [%1];" : "=l"(w[kt4][1]) : "l"(p + 1));
                    asm volatile("ld.relaxed.gpu.global.u64 %0, [%1];" : "=l"(w[kt4][2]) : "l"(p + 8));
                    asm volatile("ld.relaxed.gpu.global.u64 %0, [%1];" : "=l"(w[kt4][3]) : "l"(p + 9));
                    #pragma unroll
                    for (int e = 0; e < 4; e++)
                        ok &= ((unsigned)(w[kt4][e] >> 32) == tgt);
                }
            } while (__ballot_sync(0xffffffffu, !ok));
        }

        // ---- tensor-core GEMV (PRMT unpack of pre-split words) ----
        float d[3][4];
        #pragma unroll
        for (int m = 0; m < 3; m++)
            #pragma unroll
            for (int e = 0; e < 4; e++) d[m][e] = 0.0f;

        #pragma unroll
        for (int kt4 = 0; kt4 < 4; kt4++) {
            unsigned p0 = (unsigned)w[kt4][0], p1 = (unsigned)w[kt4][1];
            unsigned p2 = (unsigned)w[kt4][2], p3 = (unsigned)w[kt4][3];
            unsigned bh0 = prmtb(p0, p1, 0x5410), bl0 = prmtb(p0, p1, 0x7632);
            unsigned bh1 = prmtb(p2, p3, 0x5410), bl1 = prmtb(p2, p3, 0x7632);
            #pragma unroll
            for (int m = 0; m < 3; m++) {
                mma_bf16(d[m], awhi[m][kt4], bh0, bh1);
                mma_bf16(d[m], awhi[m][kt4], bl0, bl1);
                mma_bf16(d[m], awlo[m][kt4], bh0, bh1);
            }
        }
        {
            float* rb = red[t & 1];
            #pragma unroll
            for (int m = 0; m < 3; m++) {
                float* rp = rb + (warp*3 + m)*RMT + (lane>>2)*RROW + (lane&3)*2;
                *(float2*)rp            = make_float2(d[m][0], d[m][1]);
                *(float2*)(rp + 8*RROW) = make_float2(d[m][2], d[m][3]);
            }
        }
        __syncthreads();

        // ---- fused reduce + gate math + publish (tid<128) ----
        if (tid < 128) {
            const float* rb = red[t & 1];
            float gh[3];
            #pragma unroll
            for (int g = 0; g < 3; g++) {
                const float* rp = rb + g*RMT + gjj*RROW + gb;
                float s = 0.0f;
                #pragma unroll
                for (int w8 = 0; w8 < 8; w8++)
                    s += rp[w8*3*RMT];
                gh[g] = s + bh_sm[g*16 + gjj];
            }
            float r  = sigf(gxr + gh[0]);
            float zg = sigf(gxz + gh[1]);
            float n  = tanhfast(gxn + r*gh[2]);
            float hn2 = (1.0f - zg)*n + zg*h_prev;
            h_prev = hn2;

            __nv_bfloat16 hi, lo;
            split1(hn2, hi, lo);
            unsigned pk = (unsigned)*reinterpret_cast<unsigned short*>(&hi)
                        | ((unsigned)*reinterpret_cast<unsigned short*>(&lo) << 16);

            if (t < TT - 1) {
                // publish FIRST (critical path for the whole group)
                unsigned long long word =
                    ((unsigned long long)(base + (unsigned)(t + 1)) << 32) | pk;
                unsigned long long* hp = &g_hs[grp][(t + 1) & 1][gb*HO + jbase + gjj];
                asm volatile("st.relaxed.gpu.global.u64 [%0], %1;" :: "l"(hp), "l"(word));
            }
            // off-path: y store + gx(t+1) prefetch
            size_t idx = ((size_t)b_glob*TT + t)*HO + jbase + gjj;
            if (dst_mode == 2) {
                dout[idx] = (t < slen) ? hn2 : 0.0f;
            } else {
                g_ahi[idx] = hi;
                g_alo[idx] = lo;
            }
            if (t < TT - 1) {
                size_t bse = ((size_t)b_glob*TT + (t + 1))*G3 + jbase + gjj;
                gxr = g_gx[bse];
                gxz = g_gx[bse + HO];
                gxn = g_gx[bse + 2*HO];
            }
        }
        // no trailing sync: red is double-buffered; cross-iter ordering is via
        // the single barrier (gate reads of red[t&1] precede sync(t+1), any
        // warp's next write of red[t&1] is at iter t+2, after sync(t+1)).
    }
    if (tid == 0) g_epoch[grp][cig][0] = base + TT;
}

// ---------------- launch ----------------------------------------------------
#define GEMM_SMEM (2*768*GLDA*2)

extern "C" void kernel_launch(void* const* d_in, const int* in_sizes, int n_in,
                              void* d_out, int out_size) {
    const float* z     = (const float*)d_in[0];
    const int*   seq   = (const int*)  d_in[1];
    const float* chord = (const float*)d_in[2];
    const float* fc_w  = (const float*)d_in[3];
    const float* fc_b  = (const float*)d_in[4];
    const float* w_ih0 = (const float*)d_in[5];
    const float* w_hh0 = (const float*)d_in[6];
    const float* b_ih0 = (const float*)d_in[7];
    const float* b_hh0 = (const float*)d_in[8];
    const float* w_ih1 = (const float*)d_in[9];
    const float* w_hh1 = (const float*)d_in[10];
    const float* b_ih1 = (const float*)d_in[11];
    const float* b_hh1 = (const float*)d_in[12];
    const float* w_ih2 = (const float*)d_in[13];
    const float* w_hh2 = (const float*)d_in[14];
    const float* b_ih2 = (const float*)d_in[15];
    const float* b_hh2 = (const float*)d_in[16];
    float* out = (float*)d_out;

    cudaFuncSetAttribute(gemm_bf16<HID>, cudaFuncAttributeMaxDynamicSharedMemorySize, GEMM_SMEM);
    cudaFuncSetAttribute(gemm_bf16<HO>,  cudaFuncAttributeMaxDynamicSharedMemorySize, GEMM_SMEM);

    dim3 ggrid(G3/256, MTOT/128);   // (6, 128)

    fc_kernel<<<BB, LAT>>>(z, fc_w, fc_b);
    split_a0<<<(int)(((size_t)MTOT*HID)/1024), 256>>>(chord);

    split_w<<<(G3*HID)/1024, 256>>>(w_ih0, G3*HID);
    gemm_bf16<HID><<<ggrid, 256, GEMM_SMEM>>>(b_ih0);
    gru6<<<NG*CPG, 256>>>(w_hh0, b_hh0, nullptr, seq, 0);

    split_w<<<(G3*HO)/1024, 256>>>(w_ih1, G3*HO);
    gemm_bf16<HO><<<ggrid, 256, GEMM_SMEM>>>(b_ih1);
    gru6<<<NG*CPG, 256>>>(w_hh1, b_hh1, nullptr, seq, 1);

    split_w<<<(G3*HO)/1024, 256>>>(w_ih2, G3*HO);
    gemm_bf16<HO><<<ggrid, 256, GEMM_SMEM>>>(b_ih2);
    gru6<<<NG*CPG, 256>>>(w_hh2, b_hh2, out, seq, 2);
}